// round 1
// baseline (speedup 1.0000x reference)
#include <cuda_runtime.h>

#define BDIM 2
#define TSEQ 2048
#define NH 16
#define HD 64
#define DM 1024
#define MTOT (BDIM*TSEQ)

// Scratch (allocation-free contract: __device__ globals)
__device__ float g_q[BDIM*NH*TSEQ*HD];
__device__ float g_k[BDIM*NH*TSEQ*HD];
__device__ float g_v[BDIM*NH*TSEQ*HD];
__device__ float g_attn[(size_t)MTOT*DM];

// ---------------------------------------------------------------------------
// SGEMM: C[m,n] = sum_k A[m,k] * W[n,k] + bias[n]
// A: [M,K] row-major, W: [N,K] row-major. BM=BN=128, BK=8, 256 threads, 8x8/thread.
// SCATTER=true: scatter into g_q/g_k/g_v with [b][h][t][d] layout (QKV proj).
// ---------------------------------------------------------------------------
template<bool SCATTER>
__global__ __launch_bounds__(256)
void sgemm_kernel(const float* __restrict__ A, const float* __restrict__ W,
                  const float* __restrict__ bias, float* __restrict__ C,
                  int N, int K)
{
    __shared__ float As[8][132];   // As[k][m], pad 132 -> conflict-free transpose store
    __shared__ float Bs[8][132];   // Bs[k][n]

    const int tid = threadIdx.x;
    const int tx  = tid & 15;
    const int ty  = tid >> 4;
    const int m0  = blockIdx.y * 128;
    const int n0  = blockIdx.x * 128;

    const int lr = tid >> 1;          // 0..127: tile row
    const int lk = (tid & 1) << 2;    // 0 or 4: k quad

    const float* Ap = A + (size_t)(m0 + lr) * K + lk;
    const float* Wp = W + (size_t)(n0 + lr) * K + lk;

    float acc[8][8];
    #pragma unroll
    for (int i = 0; i < 8; i++)
        #pragma unroll
        for (int j = 0; j < 8; j++) acc[i][j] = 0.f;

    for (int k0 = 0; k0 < K; k0 += 8) {
        float4 av = *(const float4*)(Ap + k0);
        float4 wv = *(const float4*)(Wp + k0);
        As[lk+0][lr] = av.x; As[lk+1][lr] = av.y; As[lk+2][lr] = av.z; As[lk+3][lr] = av.w;
        Bs[lk+0][lr] = wv.x; Bs[lk+1][lr] = wv.y; Bs[lk+2][lr] = wv.z; Bs[lk+3][lr] = wv.w;
        __syncthreads();

        #pragma unroll
        for (int kk = 0; kk < 8; kk++) {
            float4 a0 = *(const float4*)&As[kk][ty*4];
            float4 a1 = *(const float4*)&As[kk][64 + ty*4];
            float4 b0 = *(const float4*)&Bs[kk][tx*4];
            float4 b1 = *(const float4*)&Bs[kk][64 + tx*4];
            float a[8] = {a0.x,a0.y,a0.z,a0.w,a1.x,a1.y,a1.z,a1.w};
            float b[8] = {b0.x,b0.y,b0.z,b0.w,b1.x,b1.y,b1.z,b1.w};
            #pragma unroll
            for (int i = 0; i < 8; i++)
                #pragma unroll
                for (int j = 0; j < 8; j++)
                    acc[i][j] += a[i] * b[j];
        }
        __syncthreads();
    }

    // Epilogue (split-tile mapping: row = ig*64 + ty*4 + ii, col = jg*64 + tx*4 + jj)
    #pragma unroll
    for (int ig = 0; ig < 2; ig++) {
        #pragma unroll
        for (int ii = 0; ii < 4; ii++) {
            int m = m0 + ig*64 + ty*4 + ii;
            #pragma unroll
            for (int jg = 0; jg < 2; jg++) {
                int n = n0 + jg*64 + tx*4;
                float4 r;
                r.x = acc[ig*4+ii][jg*4+0] + bias[n+0];
                r.y = acc[ig*4+ii][jg*4+1] + bias[n+1];
                r.z = acc[ig*4+ii][jg*4+2] + bias[n+2];
                r.w = acc[ig*4+ii][jg*4+3] + bias[n+3];
                if (!SCATTER) {
                    *(float4*)&C[(size_t)m * N + n] = r;
                } else {
                    // n -> (mat, h, d); m -> (b, t). 64-col groups never cross head/mat.
                    int mat = n >> 10;
                    int h   = (n >> 6) & 15;
                    int d   = n & 63;
                    int b   = m >> 11;
                    int t   = m & 2047;
                    float* dst = (mat == 0) ? g_q : (mat == 1) ? g_k : g_v;
                    *(float4*)&dst[(((b*NH + h)*TSEQ) + t)*HD + d] = r;
                }
            }
        }
    }
}

// ---------------------------------------------------------------------------
// Causal flash attention, fp32. One CTA = 64 q rows of one (b,h).
// 256 threads (16x16), 4x4 micro-tile. Online softmax.
// smem: Qs[64][64], Kt[64][68] (K transposed: Kt[d][c]), Vs[64][64], Ps[64][68]
// ---------------------------------------------------------------------------
__global__ __launch_bounds__(256)
void flash_kernel(const float* __restrict__ Q, const float* __restrict__ K,
                  const float* __restrict__ V, float* __restrict__ O)
{
    extern __shared__ float sm[];
    float* Qs = sm;                 // 64*64
    float* Kt = sm + 64*64;         // 64*68
    float* Vs = Kt + 64*68;         // 64*64
    float* Ps = Vs + 64*64;         // 64*68

    const int tid = threadIdx.x;
    const int tx  = tid & 15;
    const int ty  = tid >> 4;
    const int qb  = blockIdx.x;
    const int bh  = blockIdx.y;
    const int qbase = qb * 64;

    const float* Qp = Q + (size_t)bh * TSEQ * HD;
    const float* Kp = K + (size_t)bh * TSEQ * HD;
    const float* Vp = V + (size_t)bh * TSEQ * HD;

    // Load Q tile, pre-scaled by 1/sqrt(Hd) = 0.125
    for (int i = tid; i < 1024; i += 256) {
        int r  = i >> 4;
        int c4 = (i & 15) << 2;
        float4 qv = *(const float4*)&Qp[(size_t)(qbase + r)*HD + c4];
        qv.x *= 0.125f; qv.y *= 0.125f; qv.z *= 0.125f; qv.w *= 0.125f;
        *(float4*)&Qs[r*64 + c4] = qv;
    }

    float m_i[4], l_i[4], acc[4][4];
    #pragma unroll
    for (int i = 0; i < 4; i++) {
        m_i[i] = -1e30f; l_i[i] = 0.f;
        #pragma unroll
        for (int j = 0; j < 4; j++) acc[i][j] = 0.f;
    }

    for (int kb = 0; kb <= qb; kb++) {
        const int kbase = kb * 64;
        __syncthreads();  // previous PV reads done (also covers Q-load on iter 0)

        // K tile transposed (coalesced global read, ~4-way STS conflict, once/tile)
        for (int i = tid; i < 4096; i += 256) {
            int c = i >> 6, d = i & 63;
            Kt[d*68 + c] = Kp[(size_t)(kbase + c)*HD + d];
        }
        // V tile natural, float4
        for (int i = tid; i < 1024; i += 256) {
            int c = i >> 4, d4 = (i & 15) << 2;
            *(float4*)&Vs[c*64 + d4] = *(const float4*)&Vp[(size_t)(kbase + c)*HD + d4];
        }
        __syncthreads();

        // S = Q K^T (4x4 per thread)
        float s[4][4];
        #pragma unroll
        for (int i = 0; i < 4; i++)
            #pragma unroll
            for (int j = 0; j < 4; j++) s[i][j] = 0.f;

        #pragma unroll 8
        for (int d = 0; d < 64; d++) {
            float4 b4 = *(const float4*)&Kt[d*68 + tx*4];
            float b[4] = {b4.x, b4.y, b4.z, b4.w};
            #pragma unroll
            for (int i = 0; i < 4; i++) {
                float a = Qs[(ty*4 + i)*64 + d];
                #pragma unroll
                for (int j = 0; j < 4; j++) s[i][j] += a * b[j];
            }
        }

        // Causal mask (diagonal block only)
        if (kb == qb) {
            #pragma unroll
            for (int i = 0; i < 4; i++) {
                int r = ty*4 + i;
                #pragma unroll
                for (int j = 0; j < 4; j++)
                    if (tx*4 + j > r) s[i][j] = -1e30f;
            }
        }

        // Online softmax (row groups = 16-lane shuffle segments)
        #pragma unroll
        for (int i = 0; i < 4; i++) {
            float mx = fmaxf(fmaxf(s[i][0], s[i][1]), fmaxf(s[i][2], s[i][3]));
            #pragma unroll
            for (int off = 1; off < 16; off <<= 1)
                mx = fmaxf(mx, __shfl_xor_sync(0xffffffffu, mx, off, 16));
            float mnew  = fmaxf(m_i[i], mx);
            float alpha = __expf(m_i[i] - mnew);
            float rs = 0.f;
            #pragma unroll
            for (int j = 0; j < 4; j++) { s[i][j] = __expf(s[i][j] - mnew); rs += s[i][j]; }
            #pragma unroll
            for (int off = 1; off < 16; off <<= 1)
                rs += __shfl_xor_sync(0xffffffffu, rs, off, 16);
            l_i[i] = l_i[i]*alpha + rs;
            m_i[i] = mnew;
            #pragma unroll
            for (int j = 0; j < 4; j++) acc[i][j] *= alpha;
        }

        // Stage P
        #pragma unroll
        for (int i = 0; i < 4; i++) {
            float4 pv = make_float4(s[i][0], s[i][1], s[i][2], s[i][3]);
            *(float4*)&Ps[(ty*4 + i)*68 + tx*4] = pv;
        }
        __syncthreads();

        // acc += P @ V
        #pragma unroll 8
        for (int c = 0; c < 64; c++) {
            float4 b4 = *(const float4*)&Vs[c*64 + tx*4];
            float b[4] = {b4.x, b4.y, b4.z, b4.w};
            #pragma unroll
            for (int i = 0; i < 4; i++) {
                float a = Ps[(ty*4 + i)*68 + c];
                #pragma unroll
                for (int j = 0; j < 4; j++) acc[i][j] += a * b[j];
            }
        }
    }

    // Write O in [b][t][h*64+d] layout (input layout of the out-projection)
    const int b = bh >> 4, h = bh & 15;
    #pragma unroll
    for (int i = 0; i < 4; i++) {
        int t = qbase + ty*4 + i;
        float inv = 1.f / l_i[i];
        float4 r = make_float4(acc[i][0]*inv, acc[i][1]*inv, acc[i][2]*inv, acc[i][3]*inv);
        *(float4*)&O[((size_t)(b*TSEQ + t))*DM + h*HD + tx*4] = r;
    }
}

// ---------------------------------------------------------------------------
extern "C" void kernel_launch(void* const* d_in, const int* in_sizes, int n_in,
                              void* d_out, int out_size)
{
    (void)in_sizes; (void)n_in; (void)out_size;
    const float* x     = (const float*)d_in[0];
    const float* qkv_w = (const float*)d_in[1];
    const float* qkv_b = (const float*)d_in[2];
    const float* out_w = (const float*)d_in[3];
    const float* out_b = (const float*)d_in[4];
    float* out = (float*)d_out;

    float *qp, *kp, *vp, *ap;
    cudaGetSymbolAddress((void**)&qp, g_q);
    cudaGetSymbolAddress((void**)&kp, g_k);
    cudaGetSymbolAddress((void**)&vp, g_v);
    cudaGetSymbolAddress((void**)&ap, g_attn);

    const int flash_smem = (64*64 + 64*68 + 64*64 + 64*68) * 4;  // 67584 B
    cudaFuncSetAttribute(flash_kernel, cudaFuncAttributeMaxDynamicSharedMemorySize, flash_smem);

    // 1) QKV projection, scatter into [B,H,T,Hd] Q/K/V
    dim3 g1(3072/128, MTOT/128);
    sgemm_kernel<true><<<g1, 256>>>(x, qkv_w, qkv_b, nullptr, 3072, DM);

    // 2) Causal flash attention -> g_attn in [B,T,D] layout
    dim3 g2(TSEQ/64, BDIM*NH);
    flash_kernel<<<g2, 256, flash_smem>>>(qp, kp, vp, ap);

    // 3) Output projection -> d_out
    dim3 g3(DM/128, MTOT/128);
    sgemm_kernel<false><<<g3, 256>>>(ap, out_w, out_b, out, DM, DM);
}

// round 3
// speedup vs baseline: 1.6338x; 1.6338x over previous
#include <cuda_runtime.h>
#include <cuda_bf16.h>
#include <cstdint>

#define BDIM 2
#define TSEQ 2048
#define NH 16
#define HD 64
#define DM 1024
#define MTOT (BDIM*TSEQ)

// ---------------- scratch (allocation-free: __device__ globals) ----------------
__device__ float g_q[BDIM*NH*TSEQ*HD];
__device__ float g_k[BDIM*NH*TSEQ*HD];
__device__ float g_v[BDIM*NH*TSEQ*HD];
__device__ float g_attn[(size_t)MTOT*DM];
// bf16 hi/lo splits (uint4 for 16B alignment)
__device__ uint4 g_xhi[(size_t)MTOT*DM*2/16],  g_xlo[(size_t)MTOT*DM*2/16];
__device__ uint4 g_w1hi[(size_t)3*DM*DM*2/16], g_w1lo[(size_t)3*DM*DM*2/16];
__device__ uint4 g_w2hi[(size_t)DM*DM*2/16],   g_w2lo[(size_t)DM*DM*2/16];
__device__ uint4 g_ahi[(size_t)MTOT*DM*2/16],  g_alo[(size_t)MTOT*DM*2/16];

// ---------------- helpers ----------------
__device__ __forceinline__ uint32_t smem_u32(const void* p) {
    uint32_t a;
    asm("{ .reg .u64 t; cvta.to.shared.u64 t, %1; cvt.u32.u64 %0, t; }" : "=r"(a) : "l"(p));
    return a;
}
__device__ __forceinline__ void cpasync16(uint32_t dst, const void* src) {
    asm volatile("cp.async.cg.shared.global [%0], [%1], 16;" :: "r"(dst), "l"(src) : "memory");
}
__device__ __forceinline__ void ldsm4(uint32_t* r, uint32_t addr) {
    asm volatile("ldmatrix.sync.aligned.m8n8.x4.shared.b16 {%0,%1,%2,%3}, [%4];"
        : "=r"(r[0]), "=r"(r[1]), "=r"(r[2]), "=r"(r[3]) : "r"(addr));
}
__device__ __forceinline__ void mma_bf16(float* c, const uint32_t* a, const uint32_t* b) {
    asm volatile(
        "mma.sync.aligned.m16n8k16.row.col.f32.bf16.bf16.f32 "
        "{%0,%1,%2,%3}, {%4,%5,%6,%7}, {%8,%9}, {%0,%1,%2,%3};"
        : "+f"(c[0]), "+f"(c[1]), "+f"(c[2]), "+f"(c[3])
        : "r"(a[0]), "r"(a[1]), "r"(a[2]), "r"(a[3]), "r"(b[0]), "r"(b[1]));
}

// ---------------- fp32 -> bf16 hi/lo split ----------------
__global__ __launch_bounds__(256)
void split_kernel(const float* __restrict__ s, __nv_bfloat16* __restrict__ hi,
                  __nv_bfloat16* __restrict__ lo, int n4)
{
    int i = blockIdx.x * blockDim.x + threadIdx.x;
    if (i >= n4) return;
    float4 v = ((const float4*)s)[i];
    float f[4] = {v.x, v.y, v.z, v.w};
    unsigned short h[4], l[4];
    #pragma unroll
    for (int j = 0; j < 4; j++) {
        __nv_bfloat16 hb = __float2bfloat16(f[j]);
        __nv_bfloat16 lb = __float2bfloat16(f[j] - __bfloat162float(hb));
        h[j] = reinterpret_cast<unsigned short&>(hb);
        l[j] = reinterpret_cast<unsigned short&>(lb);
    }
    ((ushort4*)hi)[i] = make_ushort4(h[0], h[1], h[2], h[3]);
    ((ushort4*)lo)[i] = make_ushort4(l[0], l[1], l[2], l[3]);
}

// ---------------- mma.sync GEMM: C[m,n] = sum_k A[m,k]*W[n,k] + bias[n] ----------------
// bf16 hi/lo 3-pass (Ahi*Whi + Ahi*Wlo + Alo*Whi), fp32 accumulate.
// BM=128, BN=128, BK=32; 8 warps (4m x 2n), warp tile 32x64 (2 m16 x 8 n8).
// smem tile: [128 rows][32 bf16 = 64B], 4 chunks of 16B, chunk XOR-swizzled by (row>>1)&3.
#define BK 32
#define NCH (DM / BK)               // 32 k-chunks
#define TILE_B 8192                 // 128*64 bytes
#define STAGE_B (4 * TILE_B)        // Ahi,Alo,Whi,Wlo
#define GEMM_SMEM (2 * STAGE_B)     // 65536

template<bool SCATTER>
__global__ __launch_bounds__(256)
void mma_gemm(const __nv_bfloat16* __restrict__ Ahi, const __nv_bfloat16* __restrict__ Alo,
              const __nv_bfloat16* __restrict__ Whi, const __nv_bfloat16* __restrict__ Wlo,
              const float* __restrict__ bias, float* __restrict__ C, int N)
{
    extern __shared__ char smem[];
    const uint32_t sbase = smem_u32(smem);
    const int tid = threadIdx.x, wid = tid >> 5, lane = tid & 31;
    const int wm = wid & 3, wn = wid >> 2;           // warp grid 4m x 2n
    const int m0 = blockIdx.y * 128, n0 = blockIdx.x * 128;
    const int K = DM;

    // cp.async stage loader: 512 (row,chunk) 16B pieces per tile, 2 per thread.
    auto load_stage = [&](int c, int stg) {
        const uint32_t st = sbase + (uint32_t)stg * STAGE_B;
        const int k0 = c * BK;
        #pragma unroll
        for (int t = 0; t < 2; t++) {
            int idx = tid + t * 256;            // 0..511
            int row = idx >> 2, ch = idx & 3;
            uint32_t so = (uint32_t)(row * 64 + ((ch ^ ((row >> 1) & 3)) * 16));
            int gk = k0 + ch * 8;
            const size_t ea = (size_t)(m0 + row) * K + gk;
            const size_t ew = (size_t)(n0 + row) * K + gk;
            cpasync16(st + so,              Ahi + ea);
            cpasync16(st + TILE_B + so,     Alo + ea);
            cpasync16(st + 2*TILE_B + so,   Whi + ew);
            cpasync16(st + 3*TILE_B + so,   Wlo + ew);
        }
        asm volatile("cp.async.commit_group;" ::: "memory");
    };

    // ldmatrix per-lane row/swizzle precompute
    // A: lanes 0-7 rows +0..7 (k lo8), 8-15 rows +8..15 (k lo8),
    //    16-23 rows +0..7 (k hi8), 24-31 rows +8..15 (k hi8)
    const int arowoff = lane & 15;
    const int akoff   = lane >> 4;            // 0/1 -> chunk +0/+1
    // B (x4 covers two n8 tiles): lanes 0-7 n+0..7 klo, 8-15 n+0..7 khi,
    //    16-23 n+8..15 klo, 24-31 n+8..15 khi
    const int browoff = (lane & 7) + ((lane >> 4) << 3);
    const int bkoff   = (lane >> 3) & 1;

    int rowA[2], swA[2];
    #pragma unroll
    for (int mt = 0; mt < 2; mt++) {
        rowA[mt] = wm * 32 + mt * 16 + arowoff;
        swA[mt]  = (rowA[mt] >> 1) & 3;
    }
    int rowB[4], swB[4];
    #pragma unroll
    for (int nt2 = 0; nt2 < 4; nt2++) {
        rowB[nt2] = wn * 64 + nt2 * 16 + browoff;
        swB[nt2]  = (rowB[nt2] >> 1) & 3;
    }

    float acc[2][8][4];
    #pragma unroll
    for (int mt = 0; mt < 2; mt++)
        #pragma unroll
        for (int nt = 0; nt < 8; nt++)
            #pragma unroll
            for (int q = 0; q < 4; q++) acc[mt][nt][q] = 0.f;

    load_stage(0, 0);

    for (int c = 0; c < NCH; c++) {
        const int cur = c & 1;
        if (c + 1 < NCH) {
            load_stage(c + 1, cur ^ 1);
            asm volatile("cp.async.wait_group 1;" ::: "memory");
        } else {
            asm volatile("cp.async.wait_group 0;" ::: "memory");
        }
        __syncthreads();

        const uint32_t st = sbase + (uint32_t)cur * STAGE_B;
        #pragma unroll
        for (int s = 0; s < 2; s++) {
            uint32_t ahi[2][4], alo[2][4];
            #pragma unroll
            for (int mt = 0; mt < 2; mt++) {
                uint32_t off = (uint32_t)(rowA[mt] * 64 + (((2*s + akoff) ^ swA[mt]) * 16));
                ldsm4(ahi[mt], st + off);
                ldsm4(alo[mt], st + TILE_B + off);
            }
            uint32_t bhi[4][4], blo[4][4];
            #pragma unroll
            for (int nt2 = 0; nt2 < 4; nt2++) {
                uint32_t off = (uint32_t)(rowB[nt2] * 64 + (((2*s + bkoff) ^ swB[nt2]) * 16));
                ldsm4(bhi[nt2], st + 2*TILE_B + off);
                ldsm4(blo[nt2], st + 3*TILE_B + off);
            }
            #pragma unroll
            for (int mt = 0; mt < 2; mt++)
                #pragma unroll
                for (int nt = 0; nt < 8; nt++) {
                    const uint32_t* bh = &bhi[nt >> 1][(nt & 1) * 2];
                    const uint32_t* bl = &blo[nt >> 1][(nt & 1) * 2];
                    mma_bf16(acc[mt][nt], ahi[mt], bh);
                    mma_bf16(acc[mt][nt], ahi[mt], bl);
                    mma_bf16(acc[mt][nt], alo[mt], bh);
                }
        }
        __syncthreads();
    }

    // Epilogue: lane holds (row=l/4 [, +8], cols 2*(l%4),+1) per mma tile.
    const int lr = lane >> 2, lc = (lane & 3) * 2;
    #pragma unroll
    for (int mt = 0; mt < 2; mt++) {
        #pragma unroll
        for (int half = 0; half < 2; half++) {
            const int m = m0 + wm * 32 + mt * 16 + lr + half * 8;
            #pragma unroll
            for (int nt = 0; nt < 8; nt++) {
                const int n = n0 + wn * 64 + nt * 8 + lc;
                float2 r;
                r.x = acc[mt][nt][half * 2 + 0] + bias[n + 0];
                r.y = acc[mt][nt][half * 2 + 1] + bias[n + 1];
                if (!SCATTER) {
                    *(float2*)&C[(size_t)m * N + n] = r;
                } else {
                    int mat = n >> 10, h = (n >> 6) & 15, d = n & 63;
                    int b = m >> 11, t = m & 2047;
                    float* dst = (mat == 0) ? g_q : (mat == 1) ? g_k : g_v;
                    *(float2*)&dst[(((size_t)(b * NH + h) * TSEQ) + t) * HD + d] = r;
                }
            }
        }
    }
}

// ---------------- Causal flash attention, fp32 (unchanged, known-correct) ----------------
__global__ __launch_bounds__(256)
void flash_kernel(const float* __restrict__ Q, const float* __restrict__ K,
                  const float* __restrict__ V, float* __restrict__ O)
{
    extern __shared__ float sm[];
    float* Qs = sm;
    float* Kt = sm + 64*64;
    float* Vs = Kt + 64*68;
    float* Ps = Vs + 64*64;

    const int tid = threadIdx.x;
    const int tx  = tid & 15;
    const int ty  = tid >> 4;
    const int qb  = blockIdx.x;
    const int bh  = blockIdx.y;
    const int qbase = qb * 64;

    const float* Qp = Q + (size_t)bh * TSEQ * HD;
    const float* Kp = K + (size_t)bh * TSEQ * HD;
    const float* Vp = V + (size_t)bh * TSEQ * HD;

    for (int i = tid; i < 1024; i += 256) {
        int r  = i >> 4;
        int c4 = (i & 15) << 2;
        float4 qv = *(const float4*)&Qp[(size_t)(qbase + r)*HD + c4];
        qv.x *= 0.125f; qv.y *= 0.125f; qv.z *= 0.125f; qv.w *= 0.125f;
        *(float4*)&Qs[r*64 + c4] = qv;
    }

    float m_i[4], l_i[4], acc[4][4];
    #pragma unroll
    for (int i = 0; i < 4; i++) {
        m_i[i] = -1e30f; l_i[i] = 0.f;
        #pragma unroll
        for (int j = 0; j < 4; j++) acc[i][j] = 0.f;
    }

    for (int kb = 0; kb <= qb; kb++) {
        const int kbase = kb * 64;
        __syncthreads();

        for (int i = tid; i < 4096; i += 256) {
            int c = i >> 6, d = i & 63;
            Kt[d*68 + c] = Kp[(size_t)(kbase + c)*HD + d];
        }
        for (int i = tid; i < 1024; i += 256) {
            int c = i >> 4, d4 = (i & 15) << 2;
            *(float4*)&Vs[c*64 + d4] = *(const float4*)&Vp[(size_t)(kbase + c)*HD + d4];
        }
        __syncthreads();

        float s[4][4];
        #pragma unroll
        for (int i = 0; i < 4; i++)
            #pragma unroll
            for (int j = 0; j < 4; j++) s[i][j] = 0.f;

        #pragma unroll 8
        for (int d = 0; d < 64; d++) {
            float4 b4 = *(const float4*)&Kt[d*68 + tx*4];
            float b[4] = {b4.x, b4.y, b4.z, b4.w};
            #pragma unroll
            for (int i = 0; i < 4; i++) {
                float a = Qs[(ty*4 + i)*64 + d];
                #pragma unroll
                for (int j = 0; j < 4; j++) s[i][j] += a * b[j];
            }
        }

        if (kb == qb) {
            #pragma unroll
            for (int i = 0; i < 4; i++) {
                int r = ty*4 + i;
                #pragma unroll
                for (int j = 0; j < 4; j++)
                    if (tx*4 + j > r) s[i][j] = -1e30f;
            }
        }

        #pragma unroll
        for (int i = 0; i < 4; i++) {
            float mx = fmaxf(fmaxf(s[i][0], s[i][1]), fmaxf(s[i][2], s[i][3]));
            #pragma unroll
            for (int off = 1; off < 16; off <<= 1)
                mx = fmaxf(mx, __shfl_xor_sync(0xffffffffu, mx, off, 16));
            float mnew  = fmaxf(m_i[i], mx);
            float alpha = __expf(m_i[i] - mnew);
            float rs = 0.f;
            #pragma unroll
            for (int j = 0; j < 4; j++) { s[i][j] = __expf(s[i][j] - mnew); rs += s[i][j]; }
            #pragma unroll
            for (int off = 1; off < 16; off <<= 1)
                rs += __shfl_xor_sync(0xffffffffu, rs, off, 16);
            l_i[i] = l_i[i]*alpha + rs;
            m_i[i] = mnew;
            #pragma unroll
            for (int j = 0; j < 4; j++) acc[i][j] *= alpha;
        }

        #pragma unroll
        for (int i = 0; i < 4; i++) {
            float4 pv = make_float4(s[i][0], s[i][1], s[i][2], s[i][3]);
            *(float4*)&Ps[(ty*4 + i)*68 + tx*4] = pv;
        }
        __syncthreads();

        #pragma unroll 8
        for (int c = 0; c < 64; c++) {
            float4 b4 = *(const float4*)&Vs[c*64 + tx*4];
            float b[4] = {b4.x, b4.y, b4.z, b4.w};
            #pragma unroll
            for (int i = 0; i < 4; i++) {
                float a = Ps[(ty*4 + i)*68 + c];
                #pragma unroll
                for (int j = 0; j < 4; j++) acc[i][j] += a * b[j];
            }
        }
    }

    const int b = bh >> 4, h = bh & 15;
    #pragma unroll
    for (int i = 0; i < 4; i++) {
        int t = qbase + ty*4 + i;
        float inv = 1.f / l_i[i];
        float4 r = make_float4(acc[i][0]*inv, acc[i][1]*inv, acc[i][2]*inv, acc[i][3]*inv);
        *(float4*)&O[((size_t)(b*TSEQ + t))*DM + h*HD + tx*4] = r;
    }
}

// ---------------------------------------------------------------------------
extern "C" void kernel_launch(void* const* d_in, const int* in_sizes, int n_in,
                              void* d_out, int out_size)
{
    (void)in_sizes; (void)n_in; (void)out_size;
    const float* x     = (const float*)d_in[0];
    const float* qkv_w = (const float*)d_in[1];
    const float* qkv_b = (const float*)d_in[2];
    const float* out_w = (const float*)d_in[3];
    const float* out_b = (const float*)d_in[4];
    float* out = (float*)d_out;

    float *qp, *kp, *vp, *ap;
    cudaGetSymbolAddress((void**)&qp, g_q);
    cudaGetSymbolAddress((void**)&kp, g_k);
    cudaGetSymbolAddress((void**)&vp, g_v);
    cudaGetSymbolAddress((void**)&ap, g_attn);
    __nv_bfloat16 *xhi, *xlo, *w1hi, *w1lo, *w2hi, *w2lo, *ahi, *alo;
    cudaGetSymbolAddress((void**)&xhi,  g_xhi);  cudaGetSymbolAddress((void**)&xlo,  g_xlo);
    cudaGetSymbolAddress((void**)&w1hi, g_w1hi); cudaGetSymbolAddress((void**)&w1lo, g_w1lo);
    cudaGetSymbolAddress((void**)&w2hi, g_w2hi); cudaGetSymbolAddress((void**)&w2lo, g_w2lo);
    cudaGetSymbolAddress((void**)&ahi,  g_ahi);  cudaGetSymbolAddress((void**)&alo,  g_alo);

    const int flash_smem = (64*64 + 64*68 + 64*64 + 64*68) * 4;
    cudaFuncSetAttribute(flash_kernel, cudaFuncAttributeMaxDynamicSharedMemorySize, flash_smem);
    cudaFuncSetAttribute(mma_gemm<true>,  cudaFuncAttributeMaxDynamicSharedMemorySize, GEMM_SMEM);
    cudaFuncSetAttribute(mma_gemm<false>, cudaFuncAttributeMaxDynamicSharedMemorySize, GEMM_SMEM);

    // 0) bf16 hi/lo splits of x and weights
    split_kernel<<<(MTOT*DM/4 + 255)/256, 256>>>(x, xhi, xlo, MTOT*DM/4);
    split_kernel<<<(3*DM*DM/4 + 255)/256, 256>>>(qkv_w, w1hi, w1lo, 3*DM*DM/4);
    split_kernel<<<(DM*DM/4 + 255)/256, 256>>>(out_w, w2hi, w2lo, DM*DM/4);

    // 1) QKV projection (mma.sync bf16 split), scatter into [B,H,T,Hd] Q/K/V (fp32)
    dim3 g1(3*DM/128, MTOT/128);
    mma_gemm<true><<<g1, 256, GEMM_SMEM>>>(xhi, xlo, w1hi, w1lo, qkv_b, nullptr, 3*DM);

    // 2) Causal flash attention -> g_attn [B,T,D] (fp32)
    dim3 g2(TSEQ/64, BDIM*NH);
    flash_kernel<<<g2, 256, flash_smem>>>(qp, kp, vp, ap);

    // 3) split attn output, then output projection -> d_out
    split_kernel<<<(MTOT*DM/4 + 255)/256, 256>>>(ap, ahi, alo, MTOT*DM/4);
    dim3 g3(DM/128, MTOT/128);
    mma_gemm<false><<<g3, 256, GEMM_SMEM>>>(ahi, alo, w2hi, w2lo, out_b, out, DM);
}

// round 4
// speedup vs baseline: 2.7870x; 1.7058x over previous
#include <cuda_runtime.h>
#include <cuda_bf16.h>
#include <cstdint>

#define BDIM 2
#define TSEQ 2048
#define NH 16
#define HD 64
#define DM 1024
#define MTOT (BDIM*TSEQ)

// ---------------- scratch (allocation-free: __device__ globals) ----------------
// bf16 hi/lo splits of inputs/weights
__device__ uint4 g_xhi[(size_t)MTOT*DM*2/16],  g_xlo[(size_t)MTOT*DM*2/16];
__device__ uint4 g_w1hi[(size_t)3*DM*DM*2/16], g_w1lo[(size_t)3*DM*DM*2/16];
__device__ uint4 g_w2hi[(size_t)DM*DM*2/16],   g_w2lo[(size_t)DM*DM*2/16];
// q/k/v in [b,h,t,d] bf16 hi/lo (q pre-scaled by 0.125)
__device__ uint4 g_qhi[(size_t)BDIM*NH*TSEQ*HD*2/16], g_qlo[(size_t)BDIM*NH*TSEQ*HD*2/16];
__device__ uint4 g_khi[(size_t)BDIM*NH*TSEQ*HD*2/16], g_klo[(size_t)BDIM*NH*TSEQ*HD*2/16];
__device__ uint4 g_vhi[(size_t)BDIM*NH*TSEQ*HD*2/16], g_vlo[(size_t)BDIM*NH*TSEQ*HD*2/16];
// attention output [b,t,1024] bf16 hi/lo
__device__ uint4 g_ahi[(size_t)MTOT*DM*2/16],  g_alo[(size_t)MTOT*DM*2/16];

// ---------------- helpers ----------------
__device__ __forceinline__ uint32_t smem_u32(const void* p) {
    uint32_t a;
    asm("{ .reg .u64 t; cvta.to.shared.u64 t, %1; cvt.u32.u64 %0, t; }" : "=r"(a) : "l"(p));
    return a;
}
__device__ __forceinline__ void cpasync16(uint32_t dst, const void* src) {
    asm volatile("cp.async.cg.shared.global [%0], [%1], 16;" :: "r"(dst), "l"(src) : "memory");
}
__device__ __forceinline__ void ldsm4(uint32_t* r, uint32_t addr) {
    asm volatile("ldmatrix.sync.aligned.m8n8.x4.shared.b16 {%0,%1,%2,%3}, [%4];"
        : "=r"(r[0]), "=r"(r[1]), "=r"(r[2]), "=r"(r[3]) : "r"(addr));
}
__device__ __forceinline__ void ldsm4t(uint32_t* r, uint32_t addr) {
    asm volatile("ldmatrix.sync.aligned.m8n8.x4.trans.shared.b16 {%0,%1,%2,%3}, [%4];"
        : "=r"(r[0]), "=r"(r[1]), "=r"(r[2]), "=r"(r[3]) : "r"(addr));
}
__device__ __forceinline__ void mma_bf16(float* c, const uint32_t* a, const uint32_t* b) {
    asm volatile(
        "mma.sync.aligned.m16n8k16.row.col.f32.bf16.bf16.f32 "
        "{%0,%1,%2,%3}, {%4,%5,%6,%7}, {%8,%9}, {%0,%1,%2,%3};"
        : "+f"(c[0]), "+f"(c[1]), "+f"(c[2]), "+f"(c[3])
        : "r"(a[0]), "r"(a[1]), "r"(a[2]), "r"(a[3]), "r"(b[0]), "r"(b[1]));
}
__device__ __forceinline__ unsigned short bfbits(__nv_bfloat16 h) {
    return reinterpret_cast<unsigned short&>(h);
}
__device__ __forceinline__ uint32_t pack_hilo(float a, float b, float* ra, float* rb) {
    __nv_bfloat16 ha = __float2bfloat16(a), hb = __float2bfloat16(b);
    *ra = a - __bfloat162float(ha);
    *rb = b - __bfloat162float(hb);
    return (uint32_t)bfbits(ha) | ((uint32_t)bfbits(hb) << 16);
}
__device__ __forceinline__ uint32_t pack_bf(float a, float b) {
    return (uint32_t)bfbits(__float2bfloat16(a)) | ((uint32_t)bfbits(__float2bfloat16(b)) << 16);
}

// ---------------- fp32 -> bf16 hi/lo split ----------------
__global__ __launch_bounds__(256)
void split_kernel(const float* __restrict__ s, __nv_bfloat16* __restrict__ hi,
                  __nv_bfloat16* __restrict__ lo, int n4)
{
    int i = blockIdx.x * blockDim.x + threadIdx.x;
    if (i >= n4) return;
    float4 v = ((const float4*)s)[i];
    float f[4] = {v.x, v.y, v.z, v.w};
    unsigned short h[4], l[4];
    #pragma unroll
    for (int j = 0; j < 4; j++) {
        __nv_bfloat16 hb = __float2bfloat16(f[j]);
        __nv_bfloat16 lb = __float2bfloat16(f[j] - __bfloat162float(hb));
        h[j] = bfbits(hb); l[j] = bfbits(lb);
    }
    ((ushort4*)hi)[i] = make_ushort4(h[0], h[1], h[2], h[3]);
    ((ushort4*)lo)[i] = make_ushort4(l[0], l[1], l[2], l[3]);
}

// ---------------- mma.sync GEMM (as round 3; SCATTER writes bf16 hi/lo qkv) ----------------
#define BK 32
#define NCH (DM / BK)
#define TILE_B 8192
#define STAGE_B (4 * TILE_B)
#define GEMM_SMEM (2 * STAGE_B)

template<bool SCATTER>
__global__ __launch_bounds__(256)
void mma_gemm(const __nv_bfloat16* __restrict__ Ahi, const __nv_bfloat16* __restrict__ Alo,
              const __nv_bfloat16* __restrict__ Whi, const __nv_bfloat16* __restrict__ Wlo,
              const float* __restrict__ bias, float* __restrict__ C, int N)
{
    extern __shared__ char smem[];
    const uint32_t sbase = smem_u32(smem);
    const int tid = threadIdx.x, wid = tid >> 5, lane = tid & 31;
    const int wm = wid & 3, wn = wid >> 2;
    const int m0 = blockIdx.y * 128, n0 = blockIdx.x * 128;
    const int K = DM;

    auto load_stage = [&](int c, int stg) {
        const uint32_t st = sbase + (uint32_t)stg * STAGE_B;
        const int k0 = c * BK;
        #pragma unroll
        for (int t = 0; t < 2; t++) {
            int idx = tid + t * 256;
            int row = idx >> 2, ch = idx & 3;
            uint32_t so = (uint32_t)(row * 64 + ((ch ^ ((row >> 1) & 3)) * 16));
            int gk = k0 + ch * 8;
            const size_t ea = (size_t)(m0 + row) * K + gk;
            const size_t ew = (size_t)(n0 + row) * K + gk;
            cpasync16(st + so,              Ahi + ea);
            cpasync16(st + TILE_B + so,     Alo + ea);
            cpasync16(st + 2*TILE_B + so,   Whi + ew);
            cpasync16(st + 3*TILE_B + so,   Wlo + ew);
        }
        asm volatile("cp.async.commit_group;" ::: "memory");
    };

    const int arowoff = lane & 15;
    const int akoff   = lane >> 4;
    const int browoff = (lane & 7) + ((lane >> 4) << 3);
    const int bkoff   = (lane >> 3) & 1;

    int rowA[2], swA[2];
    #pragma unroll
    for (int mt = 0; mt < 2; mt++) {
        rowA[mt] = wm * 32 + mt * 16 + arowoff;
        swA[mt]  = (rowA[mt] >> 1) & 3;
    }
    int rowB[4], swB[4];
    #pragma unroll
    for (int nt2 = 0; nt2 < 4; nt2++) {
        rowB[nt2] = wn * 64 + nt2 * 16 + browoff;
        swB[nt2]  = (rowB[nt2] >> 1) & 3;
    }

    float acc[2][8][4];
    #pragma unroll
    for (int mt = 0; mt < 2; mt++)
        #pragma unroll
        for (int nt = 0; nt < 8; nt++)
            #pragma unroll
            for (int q = 0; q < 4; q++) acc[mt][nt][q] = 0.f;

    load_stage(0, 0);

    for (int c = 0; c < NCH; c++) {
        const int cur = c & 1;
        if (c + 1 < NCH) {
            load_stage(c + 1, cur ^ 1);
            asm volatile("cp.async.wait_group 1;" ::: "memory");
        } else {
            asm volatile("cp.async.wait_group 0;" ::: "memory");
        }
        __syncthreads();

        const uint32_t st = sbase + (uint32_t)cur * STAGE_B;
        #pragma unroll
        for (int s = 0; s < 2; s++) {
            uint32_t ahi[2][4], alo[2][4];
            #pragma unroll
            for (int mt = 0; mt < 2; mt++) {
                uint32_t off = (uint32_t)(rowA[mt] * 64 + (((2*s + akoff) ^ swA[mt]) * 16));
                ldsm4(ahi[mt], st + off);
                ldsm4(alo[mt], st + TILE_B + off);
            }
            uint32_t bhi[4][4], blo[4][4];
            #pragma unroll
            for (int nt2 = 0; nt2 < 4; nt2++) {
                uint32_t off = (uint32_t)(rowB[nt2] * 64 + (((2*s + bkoff) ^ swB[nt2]) * 16));
                ldsm4(bhi[nt2], st + 2*TILE_B + off);
                ldsm4(blo[nt2], st + 3*TILE_B + off);
            }
            #pragma unroll
            for (int mt = 0; mt < 2; mt++)
                #pragma unroll
                for (int nt = 0; nt < 8; nt++) {
                    const uint32_t* bh = &bhi[nt >> 1][(nt & 1) * 2];
                    const uint32_t* bl = &blo[nt >> 1][(nt & 1) * 2];
                    mma_bf16(acc[mt][nt], ahi[mt], bh);
                    mma_bf16(acc[mt][nt], ahi[mt], bl);
                    mma_bf16(acc[mt][nt], alo[mt], bh);
                }
        }
        __syncthreads();
    }

    const int lr = lane >> 2, lc = (lane & 3) * 2;
    #pragma unroll
    for (int mt = 0; mt < 2; mt++) {
        #pragma unroll
        for (int half = 0; half < 2; half++) {
            const int m = m0 + wm * 32 + mt * 16 + lr + half * 8;
            #pragma unroll
            for (int nt = 0; nt < 8; nt++) {
                const int n = n0 + wn * 64 + nt * 8 + lc;
                float rx = acc[mt][nt][half * 2 + 0] + bias[n + 0];
                float ry = acc[mt][nt][half * 2 + 1] + bias[n + 1];
                if (!SCATTER) {
                    *(float2*)&C[(size_t)m * N + n] = make_float2(rx, ry);
                } else {
                    int mat = n >> 10, h = (n >> 6) & 15, d = n & 63;
                    int b = m >> 11, t = m & 2047;
                    if (mat == 0) { rx *= 0.125f; ry *= 0.125f; }
                    __nv_bfloat16 hx = __float2bfloat16(rx), hy = __float2bfloat16(ry);
                    unsigned short lx = bfbits(__float2bfloat16(rx - __bfloat162float(hx)));
                    unsigned short ly = bfbits(__float2bfloat16(ry - __bfloat162float(hy)));
                    __nv_bfloat16* dh = (mat == 0) ? (__nv_bfloat16*)g_qhi
                                       : (mat == 1) ? (__nv_bfloat16*)g_khi : (__nv_bfloat16*)g_vhi;
                    __nv_bfloat16* dl = (mat == 0) ? (__nv_bfloat16*)g_qlo
                                       : (mat == 1) ? (__nv_bfloat16*)g_klo : (__nv_bfloat16*)g_vlo;
                    size_t off = (((size_t)(b * NH + h) * TSEQ) + t) * HD + d;
                    *(ushort2*)&dh[off] = make_ushort2(bfbits(hx), bfbits(hy));
                    *(ushort2*)&dl[off] = make_ushort2(lx, ly);
                }
            }
        }
    }
}

// ---------------- flash attention via mma.sync (bf16 hi/lo 3-pass) ----------------
// CTA: 128 q rows x full head; 8 warps, each 16 q rows x 64 keys per tile.
// smem: Qhi/Qlo 128x64 bf16 (16KB each) + 2 stages x {Khi,Klo,Vhi,Vlo} (8KB each).
#define FL_QHI 0u
#define FL_QLO 16384u
#define FL_STG 32768u
#define FL_SSZ 32768u
#define FL_SMEM (FL_STG + 2 * FL_SSZ)   // 98304

__global__ __launch_bounds__(256, 1)
void flash_mma(const __nv_bfloat16* __restrict__ qhi, const __nv_bfloat16* __restrict__ qlo,
               const __nv_bfloat16* __restrict__ khi, const __nv_bfloat16* __restrict__ klo,
               const __nv_bfloat16* __restrict__ vhi, const __nv_bfloat16* __restrict__ vlo,
               __nv_bfloat16* __restrict__ ohi, __nv_bfloat16* __restrict__ olo)
{
    extern __shared__ char smem[];
    const uint32_t sb = smem_u32(smem);
    const int tid = threadIdx.x, wid = tid >> 5, lane = tid & 31;
    const int bh = blockIdx.y;
    const int qb = gridDim.x - 1 - blockIdx.x;     // heavy tiles first
    const int qbase = qb * 128;
    const size_t base = (size_t)bh * TSEQ * HD;
    const int nkb = 2 * qb + 2;

    auto ldq = [&]() {
        #pragma unroll
        for (int t = 0; t < 4; t++) {
            int idx = tid + t * 256;               // 0..1023
            int row = idx >> 3, ch = idx & 7;
            uint32_t so = (uint32_t)(row * 128 + ((ch ^ (row & 7)) * 16));
            size_t g = base + (size_t)(qbase + row) * HD + ch * 8;
            cpasync16(sb + FL_QHI + so, qhi + g);
            cpasync16(sb + FL_QLO + so, qlo + g);
        }
    };
    auto ldkv = [&](int kb, int stg) {
        const uint32_t st = sb + FL_STG + (uint32_t)stg * FL_SSZ;
        #pragma unroll
        for (int t = 0; t < 2; t++) {
            int idx = tid + t * 256;               // 0..511
            int row = idx >> 3, ch = idx & 7;
            uint32_t so = (uint32_t)(row * 128 + ((ch ^ (row & 7)) * 16));
            size_t g = base + (size_t)(kb * 64 + row) * HD + ch * 8;
            cpasync16(st + so,          khi + g);
            cpasync16(st + 8192 + so,   klo + g);
            cpasync16(st + 16384 + so,  vhi + g);
            cpasync16(st + 24576 + so,  vlo + g);
        }
        asm volatile("cp.async.commit_group;" ::: "memory");
    };

    ldq();
    ldkv(0, 0);

    // fragment addressing
    const int arow = wid * 16 + (lane & 15);       // Q rows
    const int akoff = lane >> 4;
    const int brow_off = (lane & 7) + ((lane >> 4) << 3);   // K frag rows
    const int bkoff = (lane >> 3) & 1;
    const int vrow_off = (lane & 7) + (((lane >> 3) & 1) << 3); // V trans rows
    const int vcg = lane >> 4;

    uint32_t qh[4][4], ql[4][4];
    float acc_o[8][4];
    #pragma unroll
    for (int nt = 0; nt < 8; nt++)
        #pragma unroll
        for (int q = 0; q < 4; q++) acc_o[nt][q] = 0.f;
    float m0 = -1e30f, m1 = -1e30f, l0 = 0.f, l1 = 0.f;

    const int r0g = qbase + wid * 16 + (lane >> 2);
    const int r1g = r0g + 8;

    for (int kb = 0; kb < nkb; kb++) {
        const int cur = kb & 1;
        if (kb + 1 < nkb) {
            ldkv(kb + 1, cur ^ 1);
            asm volatile("cp.async.wait_group 1;" ::: "memory");
        } else {
            asm volatile("cp.async.wait_group 0;" ::: "memory");
        }
        __syncthreads();

        if (kb == 0) {
            #pragma unroll
            for (int s4 = 0; s4 < 4; s4++) {
                uint32_t off = (uint32_t)(arow * 128 + (((2*s4 + akoff) ^ (arow & 7)) * 16));
                ldsm4(qh[s4], sb + FL_QHI + off);
                ldsm4(ql[s4], sb + FL_QLO + off);
            }
        }

        const uint32_t st = sb + FL_STG + (uint32_t)cur * FL_SSZ;

        // S = Q K^T (3-pass), acc fp32
        float s[8][4];
        #pragma unroll
        for (int nt = 0; nt < 8; nt++)
            #pragma unroll
            for (int q = 0; q < 4; q++) s[nt][q] = 0.f;

        #pragma unroll
        for (int s4 = 0; s4 < 4; s4++) {
            uint32_t kh[4][4], kl[4][4];
            #pragma unroll
            for (int nt2 = 0; nt2 < 4; nt2++) {
                int row = nt2 * 16 + brow_off;
                uint32_t off = (uint32_t)(row * 128 + (((2*s4 + bkoff) ^ (row & 7)) * 16));
                ldsm4(kh[nt2], st + off);
                ldsm4(kl[nt2], st + 8192 + off);
            }
            #pragma unroll
            for (int nt = 0; nt < 8; nt++) {
                const uint32_t* bh_ = &kh[nt >> 1][(nt & 1) * 2];
                const uint32_t* bl_ = &kl[nt >> 1][(nt & 1) * 2];
                mma_bf16(s[nt], qh[s4], bh_);
                mma_bf16(s[nt], qh[s4], bl_);
                mma_bf16(s[nt], ql[s4], bh_);
            }
        }

        // causal mask (only last two key tiles overlap the diagonal)
        const int kbase = kb * 64;
        if (kb >= nkb - 2) {
            #pragma unroll
            for (int nt = 0; nt < 8; nt++) {
                int kg0 = kbase + nt * 8 + 2 * (lane & 3);
                if (kg0 > r0g)     s[nt][0] = -1e30f;
                if (kg0 + 1 > r0g) s[nt][1] = -1e30f;
                if (kg0 > r1g)     s[nt][2] = -1e30f;
                if (kg0 + 1 > r1g) s[nt][3] = -1e30f;
            }
        }

        // online softmax (rows r0g, r1g; 4 lanes per row)
        float mx0 = -1e30f, mx1 = -1e30f;
        #pragma unroll
        for (int nt = 0; nt < 8; nt++) {
            mx0 = fmaxf(mx0, fmaxf(s[nt][0], s[nt][1]));
            mx1 = fmaxf(mx1, fmaxf(s[nt][2], s[nt][3]));
        }
        mx0 = fmaxf(mx0, __shfl_xor_sync(0xffffffffu, mx0, 1));
        mx0 = fmaxf(mx0, __shfl_xor_sync(0xffffffffu, mx0, 2));
        mx1 = fmaxf(mx1, __shfl_xor_sync(0xffffffffu, mx1, 1));
        mx1 = fmaxf(mx1, __shfl_xor_sync(0xffffffffu, mx1, 2));
        float mn0 = fmaxf(m0, mx0), mn1 = fmaxf(m1, mx1);
        float a0 = __expf(m0 - mn0), a1 = __expf(m1 - mn1);
        float sum0 = 0.f, sum1 = 0.f;
        #pragma unroll
        for (int nt = 0; nt < 8; nt++) {
            s[nt][0] = __expf(s[nt][0] - mn0);
            s[nt][1] = __expf(s[nt][1] - mn0);
            s[nt][2] = __expf(s[nt][2] - mn1);
            s[nt][3] = __expf(s[nt][3] - mn1);
            sum0 += s[nt][0] + s[nt][1];
            sum1 += s[nt][2] + s[nt][3];
        }
        sum0 += __shfl_xor_sync(0xffffffffu, sum0, 1);
        sum0 += __shfl_xor_sync(0xffffffffu, sum0, 2);
        sum1 += __shfl_xor_sync(0xffffffffu, sum1, 1);
        sum1 += __shfl_xor_sync(0xffffffffu, sum1, 2);
        l0 = l0 * a0 + sum0; m0 = mn0;
        l1 = l1 * a1 + sum1; m1 = mn1;
        #pragma unroll
        for (int nt = 0; nt < 8; nt++) {
            acc_o[nt][0] *= a0; acc_o[nt][1] *= a0;
            acc_o[nt][2] *= a1; acc_o[nt][3] *= a1;
        }

        // P fragments (hi/lo) from S accumulator layout
        uint32_t phi[4][4], plo[4][4];
        #pragma unroll
        for (int j2 = 0; j2 < 4; j2++) {
            float r0a, r0b, r1a, r1b, r2a, r2b, r3a, r3b;
            phi[j2][0] = pack_hilo(s[2*j2][0],   s[2*j2][1],   &r0a, &r0b);
            phi[j2][1] = pack_hilo(s[2*j2][2],   s[2*j2][3],   &r1a, &r1b);
            phi[j2][2] = pack_hilo(s[2*j2+1][0], s[2*j2+1][1], &r2a, &r2b);
            phi[j2][3] = pack_hilo(s[2*j2+1][2], s[2*j2+1][3], &r3a, &r3b);
            plo[j2][0] = pack_bf(r0a, r0b);
            plo[j2][1] = pack_bf(r1a, r1b);
            plo[j2][2] = pack_bf(r2a, r2b);
            plo[j2][3] = pack_bf(r3a, r3b);
        }

        // acc_o += P @ V (3-pass), V fragments via ldmatrix.trans
        #pragma unroll
        for (int j2 = 0; j2 < 4; j2++) {
            int vrow = j2 * 16 + vrow_off;
            #pragma unroll
            for (int g = 0; g < 4; g++) {
                int cg = g * 2 + vcg;
                uint32_t off = (uint32_t)(vrow * 128 + ((cg ^ (vrow & 7)) * 16));
                uint32_t vh[4], vl[4];
                ldsm4t(vh, st + 16384 + off);
                ldsm4t(vl, st + 24576 + off);
                mma_bf16(acc_o[2*g],     phi[j2], &vh[0]);
                mma_bf16(acc_o[2*g],     phi[j2], &vl[0]);
                mma_bf16(acc_o[2*g],     plo[j2], &vh[0]);
                mma_bf16(acc_o[2*g + 1], phi[j2], &vh[2]);
                mma_bf16(acc_o[2*g + 1], phi[j2], &vl[2]);
                mma_bf16(acc_o[2*g + 1], plo[j2], &vh[2]);
            }
        }
        __syncthreads();
    }

    // epilogue: normalize, split hi/lo, write [b, t, h*64+d]
    const int b = bh >> 4, h = bh & 15;
    const float inv0 = 1.f / l0, inv1 = 1.f / l1;
    #pragma unroll
    for (int nt = 0; nt < 8; nt++) {
        int d = nt * 8 + 2 * (lane & 3);
        float f0 = acc_o[nt][0] * inv0, f1 = acc_o[nt][1] * inv0;
        float f2 = acc_o[nt][2] * inv1, f3 = acc_o[nt][3] * inv1;
        size_t o0 = ((size_t)(b * TSEQ + r0g)) * DM + h * HD + d;
        size_t o1 = ((size_t)(b * TSEQ + r1g)) * DM + h * HD + d;
        __nv_bfloat16 h0 = __float2bfloat16(f0), h1 = __float2bfloat16(f1);
        __nv_bfloat16 h2 = __float2bfloat16(f2), h3 = __float2bfloat16(f3);
        *(ushort2*)&ohi[o0] = make_ushort2(bfbits(h0), bfbits(h1));
        *(ushort2*)&ohi[o1] = make_ushort2(bfbits(h2), bfbits(h3));
        *(ushort2*)&olo[o0] = make_ushort2(
            bfbits(__float2bfloat16(f0 - __bfloat162float(h0))),
            bfbits(__float2bfloat16(f1 - __bfloat162float(h1))));
        *(ushort2*)&olo[o1] = make_ushort2(
            bfbits(__float2bfloat16(f2 - __bfloat162float(h2))),
            bfbits(__float2bfloat16(f3 - __bfloat162float(h3))));
    }
}

// ---------------------------------------------------------------------------
extern "C" void kernel_launch(void* const* d_in, const int* in_sizes, int n_in,
                              void* d_out, int out_size)
{
    (void)in_sizes; (void)n_in; (void)out_size;
    const float* x     = (const float*)d_in[0];
    const float* qkv_w = (const float*)d_in[1];
    const float* qkv_b = (const float*)d_in[2];
    const float* out_w = (const float*)d_in[3];
    const float* out_b = (const float*)d_in[4];
    float* out = (float*)d_out;

    __nv_bfloat16 *xhi, *xlo, *w1hi, *w1lo, *w2hi, *w2lo, *ahi, *alo;
    __nv_bfloat16 *qhi, *qlo, *khi, *klo, *vhi, *vlo;
    cudaGetSymbolAddress((void**)&xhi,  g_xhi);  cudaGetSymbolAddress((void**)&xlo,  g_xlo);
    cudaGetSymbolAddress((void**)&w1hi, g_w1hi); cudaGetSymbolAddress((void**)&w1lo, g_w1lo);
    cudaGetSymbolAddress((void**)&w2hi, g_w2hi); cudaGetSymbolAddress((void**)&w2lo, g_w2lo);
    cudaGetSymbolAddress((void**)&ahi,  g_ahi);  cudaGetSymbolAddress((void**)&alo,  g_alo);
    cudaGetSymbolAddress((void**)&qhi,  g_qhi);  cudaGetSymbolAddress((void**)&qlo,  g_qlo);
    cudaGetSymbolAddress((void**)&khi,  g_khi);  cudaGetSymbolAddress((void**)&klo,  g_klo);
    cudaGetSymbolAddress((void**)&vhi,  g_vhi);  cudaGetSymbolAddress((void**)&vlo,  g_vlo);

    cudaFuncSetAttribute(mma_gemm<true>,  cudaFuncAttributeMaxDynamicSharedMemorySize, GEMM_SMEM);
    cudaFuncSetAttribute(mma_gemm<false>, cudaFuncAttributeMaxDynamicSharedMemorySize, GEMM_SMEM);
    cudaFuncSetAttribute(flash_mma, cudaFuncAttributeMaxDynamicSharedMemorySize, FL_SMEM);

    // 0) bf16 hi/lo splits of x and weights
    split_kernel<<<(MTOT*DM/4 + 255)/256, 256>>>(x, xhi, xlo, MTOT*DM/4);
    split_kernel<<<(3*DM*DM/4 + 255)/256, 256>>>(qkv_w, w1hi, w1lo, 3*DM*DM/4);
    split_kernel<<<(DM*DM/4 + 255)/256, 256>>>(out_w, w2hi, w2lo, DM*DM/4);

    // 1) QKV projection -> bf16 hi/lo q(k,v) in [B,H,T,Hd], q pre-scaled
    dim3 g1(3*DM/128, MTOT/128);
    mma_gemm<true><<<g1, 256, GEMM_SMEM>>>(xhi, xlo, w1hi, w1lo, qkv_b, nullptr, 3*DM);

    // 2) flash attention (tensorized) -> g_ahi/g_alo [B,T,D]
    dim3 g2(TSEQ/128, BDIM*NH);
    flash_mma<<<g2, 256, FL_SMEM>>>(qhi, qlo, khi, klo, vhi, vlo, ahi, alo);

    // 3) output projection -> d_out
    dim3 g3(DM/128, MTOT/128);
    mma_gemm<false><<<g3, 256, GEMM_SMEM>>>(ahi, alo, w2hi, w2lo, out_b, out, DM);
}

// round 5
// speedup vs baseline: 3.0508x; 1.0947x over previous
#include <cuda_runtime.h>
#include <cuda_bf16.h>
#include <cstdint>

#define BDIM 2
#define TSEQ 2048
#define NH 16
#define HD 64
#define DM 1024
#define MTOT (BDIM*TSEQ)

// ---------------- scratch (allocation-free: __device__ globals) ----------------
__device__ uint4 g_xhi[(size_t)MTOT*DM*2/16],  g_xlo[(size_t)MTOT*DM*2/16];
__device__ uint4 g_w1hi[(size_t)3*DM*DM*2/16], g_w1lo[(size_t)3*DM*DM*2/16];
__device__ uint4 g_w2hi[(size_t)DM*DM*2/16],   g_w2lo[(size_t)DM*DM*2/16];
__device__ uint4 g_qhi[(size_t)BDIM*NH*TSEQ*HD*2/16], g_qlo[(size_t)BDIM*NH*TSEQ*HD*2/16];
__device__ uint4 g_khi[(size_t)BDIM*NH*TSEQ*HD*2/16], g_klo[(size_t)BDIM*NH*TSEQ*HD*2/16];
__device__ uint4 g_vhi[(size_t)BDIM*NH*TSEQ*HD*2/16], g_vlo[(size_t)BDIM*NH*TSEQ*HD*2/16];
__device__ uint4 g_ahi[(size_t)MTOT*DM*2/16],  g_alo[(size_t)MTOT*DM*2/16];

// ---------------- helpers ----------------
__device__ __forceinline__ uint32_t smem_u32(const void* p) {
    uint32_t a;
    asm("{ .reg .u64 t; cvta.to.shared.u64 t, %1; cvt.u32.u64 %0, t; }" : "=r"(a) : "l"(p));
    return a;
}
__device__ __forceinline__ void cpasync16(uint32_t dst, const void* src) {
    asm volatile("cp.async.cg.shared.global [%0], [%1], 16;" :: "r"(dst), "l"(src) : "memory");
}
__device__ __forceinline__ void ldsm4(uint32_t* r, uint32_t addr) {
    asm volatile("ldmatrix.sync.aligned.m8n8.x4.shared.b16 {%0,%1,%2,%3}, [%4];"
        : "=r"(r[0]), "=r"(r[1]), "=r"(r[2]), "=r"(r[3]) : "r"(addr));
}
__device__ __forceinline__ void ldsm4t(uint32_t* r, uint32_t addr) {
    asm volatile("ldmatrix.sync.aligned.m8n8.x4.trans.shared.b16 {%0,%1,%2,%3}, [%4];"
        : "=r"(r[0]), "=r"(r[1]), "=r"(r[2]), "=r"(r[3]) : "r"(addr));
}
__device__ __forceinline__ void mma_bf16(float* c, const uint32_t* a, const uint32_t* b) {
    asm volatile(
        "mma.sync.aligned.m16n8k16.row.col.f32.bf16.bf16.f32 "
        "{%0,%1,%2,%3}, {%4,%5,%6,%7}, {%8,%9}, {%0,%1,%2,%3};"
        : "+f"(c[0]), "+f"(c[1]), "+f"(c[2]), "+f"(c[3])
        : "r"(a[0]), "r"(a[1]), "r"(a[2]), "r"(a[3]), "r"(b[0]), "r"(b[1]));
}
__device__ __forceinline__ unsigned short bfbits(__nv_bfloat16 h) {
    return reinterpret_cast<unsigned short&>(h);
}
__device__ __forceinline__ uint32_t pack_hilo(float a, float b, float* ra, float* rb) {
    __nv_bfloat16 ha = __float2bfloat16(a), hb = __float2bfloat16(b);
    *ra = a - __bfloat162float(ha);
    *rb = b - __bfloat162float(hb);
    return (uint32_t)bfbits(ha) | ((uint32_t)bfbits(hb) << 16);
}
__device__ __forceinline__ uint32_t pack_bf(float a, float b) {
    return (uint32_t)bfbits(__float2bfloat16(a)) | ((uint32_t)bfbits(__float2bfloat16(b)) << 16);
}

// ---------------- fp32 -> bf16 hi/lo split ----------------
__global__ __launch_bounds__(256)
void split_kernel(const float* __restrict__ s, __nv_bfloat16* __restrict__ hi,
                  __nv_bfloat16* __restrict__ lo, int n4)
{
    int i = blockIdx.x * blockDim.x + threadIdx.x;
    if (i >= n4) return;
    float4 v = ((const float4*)s)[i];
    float f[4] = {v.x, v.y, v.z, v.w};
    unsigned short h[4], l[4];
    #pragma unroll
    for (int j = 0; j < 4; j++) {
        __nv_bfloat16 hb = __float2bfloat16(f[j]);
        __nv_bfloat16 lb = __float2bfloat16(f[j] - __bfloat162float(hb));
        h[j] = bfbits(hb); l[j] = bfbits(lb);
    }
    ((ushort4*)hi)[i] = make_ushort4(h[0], h[1], h[2], h[3]);
    ((ushort4*)lo)[i] = make_ushort4(l[0], l[1], l[2], l[3]);
}

// ---------------- mma.sync GEMM (128-reg / 2-CTA operating point) ----------------
#define BK 32
#define NCH (DM / BK)
#define TILE_B 8192
#define STAGE_B (4 * TILE_B)
#define GEMM_SMEM (2 * STAGE_B)

template<bool SCATTER>
__global__ __launch_bounds__(256, 2)
void mma_gemm(const __nv_bfloat16* __restrict__ Ahi, const __nv_bfloat16* __restrict__ Alo,
              const __nv_bfloat16* __restrict__ Whi, const __nv_bfloat16* __restrict__ Wlo,
              const float* __restrict__ bias, float* __restrict__ C, int N)
{
    extern __shared__ char smem[];
    const uint32_t sbase = smem_u32(smem);
    const int tid = threadIdx.x, wid = tid >> 5, lane = tid & 31;
    const int wm = wid & 3, wn = wid >> 2;
    const int m0 = blockIdx.y * 128, n0 = blockIdx.x * 128;
    const int K = DM;

    auto load_stage = [&](int c, int stg) {
        const uint32_t st = sbase + (uint32_t)stg * STAGE_B;
        const int k0 = c * BK;
        #pragma unroll
        for (int t = 0; t < 2; t++) {
            int idx = tid + t * 256;
            int row = idx >> 2, ch = idx & 3;
            uint32_t so = (uint32_t)(row * 64 + ((ch ^ ((row >> 1) & 3)) * 16));
            int gk = k0 + ch * 8;
            const size_t ea = (size_t)(m0 + row) * K + gk;
            const size_t ew = (size_t)(n0 + row) * K + gk;
            cpasync16(st + so,              Ahi + ea);
            cpasync16(st + TILE_B + so,     Alo + ea);
            cpasync16(st + 2*TILE_B + so,   Whi + ew);
            cpasync16(st + 3*TILE_B + so,   Wlo + ew);
        }
        asm volatile("cp.async.commit_group;" ::: "memory");
    };

    const int arowoff = lane & 15;
    const int akoff   = lane >> 4;
    const int browoff = (lane & 7) + ((lane >> 4) << 3);
    const int bkoff   = (lane >> 3) & 1;

    int rowA[2], swA[2];
    #pragma unroll
    for (int mt = 0; mt < 2; mt++) {
        rowA[mt] = wm * 32 + mt * 16 + arowoff;
        swA[mt]  = (rowA[mt] >> 1) & 3;
    }
    int rowB[4], swB[4];
    #pragma unroll
    for (int nt2 = 0; nt2 < 4; nt2++) {
        rowB[nt2] = wn * 64 + nt2 * 16 + browoff;
        swB[nt2]  = (rowB[nt2] >> 1) & 3;
    }

    float acc[2][8][4];
    #pragma unroll
    for (int mt = 0; mt < 2; mt++)
        #pragma unroll
        for (int nt = 0; nt < 8; nt++)
            #pragma unroll
            for (int q = 0; q < 4; q++) acc[mt][nt][q] = 0.f;

    load_stage(0, 0);

    for (int c = 0; c < NCH; c++) {
        const int cur = c & 1;
        if (c + 1 < NCH) {
            load_stage(c + 1, cur ^ 1);
            asm volatile("cp.async.wait_group 1;" ::: "memory");
        } else {
            asm volatile("cp.async.wait_group 0;" ::: "memory");
        }
        __syncthreads();

        const uint32_t st = sbase + (uint32_t)cur * STAGE_B;
        #pragma unroll
        for (int s = 0; s < 2; s++) {
            uint32_t ahi[2][4], alo[2][4];
            #pragma unroll
            for (int mt = 0; mt < 2; mt++) {
                uint32_t off = (uint32_t)(rowA[mt] * 64 + (((2*s + akoff) ^ swA[mt]) * 16));
                ldsm4(ahi[mt], st + off);
                ldsm4(alo[mt], st + TILE_B + off);
            }
            uint32_t bhi[4][4], blo[4][4];
            #pragma unroll
            for (int nt2 = 0; nt2 < 4; nt2++) {
                uint32_t off = (uint32_t)(rowB[nt2] * 64 + (((2*s + bkoff) ^ swB[nt2]) * 16));
                ldsm4(bhi[nt2], st + 2*TILE_B + off);
                ldsm4(blo[nt2], st + 3*TILE_B + off);
            }
            #pragma unroll
            for (int mt = 0; mt < 2; mt++)
                #pragma unroll
                for (int nt = 0; nt < 8; nt++) {
                    const uint32_t* bh = &bhi[nt >> 1][(nt & 1) * 2];
                    const uint32_t* bl = &blo[nt >> 1][(nt & 1) * 2];
                    mma_bf16(acc[mt][nt], ahi[mt], bh);
                    mma_bf16(acc[mt][nt], ahi[mt], bl);
                    mma_bf16(acc[mt][nt], alo[mt], bh);
                }
        }
        __syncthreads();
    }

    const int lr = lane >> 2, lc = (lane & 3) * 2;
    #pragma unroll
    for (int mt = 0; mt < 2; mt++) {
        #pragma unroll
        for (int half = 0; half < 2; half++) {
            const int m = m0 + wm * 32 + mt * 16 + lr + half * 8;
            #pragma unroll
            for (int nt = 0; nt < 8; nt++) {
                const int n = n0 + wn * 64 + nt * 8 + lc;
                float rx = acc[mt][nt][half * 2 + 0] + bias[n + 0];
                float ry = acc[mt][nt][half * 2 + 1] + bias[n + 1];
                if (!SCATTER) {
                    *(float2*)&C[(size_t)m * N + n] = make_float2(rx, ry);
                } else {
                    int mat = n >> 10, h = (n >> 6) & 15, d = n & 63;
                    int b = m >> 11, t = m & 2047;
                    if (mat == 0) { rx *= 0.125f; ry *= 0.125f; }
                    __nv_bfloat16 hx = __float2bfloat16(rx), hy = __float2bfloat16(ry);
                    unsigned short lx = bfbits(__float2bfloat16(rx - __bfloat162float(hx)));
                    unsigned short ly = bfbits(__float2bfloat16(ry - __bfloat162float(hy)));
                    __nv_bfloat16* dh = (mat == 0) ? (__nv_bfloat16*)g_qhi
                                       : (mat == 1) ? (__nv_bfloat16*)g_khi : (__nv_bfloat16*)g_vhi;
                    __nv_bfloat16* dl = (mat == 0) ? (__nv_bfloat16*)g_qlo
                                       : (mat == 1) ? (__nv_bfloat16*)g_klo : (__nv_bfloat16*)g_vlo;
                    size_t off = (((size_t)(b * NH + h) * TSEQ) + t) * HD + d;
                    *(ushort2*)&dh[off] = make_ushort2(bfbits(hx), bfbits(hy));
                    *(ushort2*)&dl[off] = make_ushort2(lx, ly);
                }
            }
        }
    }
}

// ---------------- flash attention via mma.sync (bf16 hi/lo 3-pass) ----------------
#define FL_QHI 0u
#define FL_QLO 16384u
#define FL_STG 32768u
#define FL_SSZ 32768u
#define FL_SMEM (FL_STG + 2 * FL_SSZ)   // 98304

__global__ __launch_bounds__(256, 1)
void flash_mma(const __nv_bfloat16* __restrict__ qhi, const __nv_bfloat16* __restrict__ qlo,
               const __nv_bfloat16* __restrict__ khi, const __nv_bfloat16* __restrict__ klo,
               const __nv_bfloat16* __restrict__ vhi, const __nv_bfloat16* __restrict__ vlo,
               __nv_bfloat16* __restrict__ ohi, __nv_bfloat16* __restrict__ olo)
{
    extern __shared__ char smem[];
    const uint32_t sb = smem_u32(smem);
    const int tid = threadIdx.x, wid = tid >> 5, lane = tid & 31;
    const int bh = blockIdx.y;
    const int qb = gridDim.x - 1 - blockIdx.x;     // heavy tiles first
    const int qbase = qb * 128;
    const size_t base = (size_t)bh * TSEQ * HD;
    const int nkb = 2 * qb + 2;

    auto ldq = [&]() {
        #pragma unroll
        for (int t = 0; t < 4; t++) {
            int idx = tid + t * 256;
            int row = idx >> 3, ch = idx & 7;
            uint32_t so = (uint32_t)(row * 128 + ((ch ^ (row & 7)) * 16));
            size_t g = base + (size_t)(qbase + row) * HD + ch * 8;
            cpasync16(sb + FL_QHI + so, qhi + g);
            cpasync16(sb + FL_QLO + so, qlo + g);
        }
    };
    auto ldkv = [&](int kb, int stg) {
        const uint32_t st = sb + FL_STG + (uint32_t)stg * FL_SSZ;
        #pragma unroll
        for (int t = 0; t < 2; t++) {
            int idx = tid + t * 256;
            int row = idx >> 3, ch = idx & 7;
            uint32_t so = (uint32_t)(row * 128 + ((ch ^ (row & 7)) * 16));
            size_t g = base + (size_t)(kb * 64 + row) * HD + ch * 8;
            cpasync16(st + so,          khi + g);
            cpasync16(st + 8192 + so,   klo + g);
            cpasync16(st + 16384 + so,  vhi + g);
            cpasync16(st + 24576 + so,  vlo + g);
        }
        asm volatile("cp.async.commit_group;" ::: "memory");
    };

    ldq();
    ldkv(0, 0);

    const int arow = wid * 16 + (lane & 15);
    const int akoff = lane >> 4;
    const int brow_off = (lane & 7) + ((lane >> 4) << 3);
    const int bkoff = (lane >> 3) & 1;
    const int vrow_off = (lane & 7) + (((lane >> 3) & 1) << 3);
    const int vcg = lane >> 4;

    uint32_t qh[4][4], ql[4][4];
    float acc_o[8][4];
    #pragma unroll
    for (int nt = 0; nt < 8; nt++)
        #pragma unroll
        for (int q = 0; q < 4; q++) acc_o[nt][q] = 0.f;
    float m0 = -1e30f, m1 = -1e30f, l0 = 0.f, l1 = 0.f;

    const int r0g = qbase + wid * 16 + (lane >> 2);
    const int r1g = r0g + 8;

    for (int kb = 0; kb < nkb; kb++) {
        const int cur = kb & 1;
        if (kb + 1 < nkb) {
            ldkv(kb + 1, cur ^ 1);
            asm volatile("cp.async.wait_group 1;" ::: "memory");
        } else {
            asm volatile("cp.async.wait_group 0;" ::: "memory");
        }
        __syncthreads();

        if (kb == 0) {
            #pragma unroll
            for (int s4 = 0; s4 < 4; s4++) {
                uint32_t off = (uint32_t)(arow * 128 + (((2*s4 + akoff) ^ (arow & 7)) * 16));
                ldsm4(qh[s4], sb + FL_QHI + off);
                ldsm4(ql[s4], sb + FL_QLO + off);
            }
        }

        const uint32_t st = sb + FL_STG + (uint32_t)cur * FL_SSZ;

        float s[8][4];
        #pragma unroll
        for (int nt = 0; nt < 8; nt++)
            #pragma unroll
            for (int q = 0; q < 4; q++) s[nt][q] = 0.f;

        #pragma unroll
        for (int s4 = 0; s4 < 4; s4++) {
            uint32_t kh[4][4], kl[4][4];
            #pragma unroll
            for (int nt2 = 0; nt2 < 4; nt2++) {
                int row = nt2 * 16 + brow_off;
                uint32_t off = (uint32_t)(row * 128 + (((2*s4 + bkoff) ^ (row & 7)) * 16));
                ldsm4(kh[nt2], st + off);
                ldsm4(kl[nt2], st + 8192 + off);
            }
            #pragma unroll
            for (int nt = 0; nt < 8; nt++) {
                const uint32_t* bh_ = &kh[nt >> 1][(nt & 1) * 2];
                const uint32_t* bl_ = &kl[nt >> 1][(nt & 1) * 2];
                mma_bf16(s[nt], qh[s4], bh_);
                mma_bf16(s[nt], qh[s4], bl_);
                mma_bf16(s[nt], ql[s4], bh_);
            }
        }

        const int kbase = kb * 64;
        if (kb >= nkb - 2) {
            #pragma unroll
            for (int nt = 0; nt < 8; nt++) {
                int kg0 = kbase + nt * 8 + 2 * (lane & 3);
                if (kg0 > r0g)     s[nt][0] = -1e30f;
                if (kg0 + 1 > r0g) s[nt][1] = -1e30f;
                if (kg0 > r1g)     s[nt][2] = -1e30f;
                if (kg0 + 1 > r1g) s[nt][3] = -1e30f;
            }
        }

        float mx0 = -1e30f, mx1 = -1e30f;
        #pragma unroll
        for (int nt = 0; nt < 8; nt++) {
            mx0 = fmaxf(mx0, fmaxf(s[nt][0], s[nt][1]));
            mx1 = fmaxf(mx1, fmaxf(s[nt][2], s[nt][3]));
        }
        mx0 = fmaxf(mx0, __shfl_xor_sync(0xffffffffu, mx0, 1));
        mx0 = fmaxf(mx0, __shfl_xor_sync(0xffffffffu, mx0, 2));
        mx1 = fmaxf(mx1, __shfl_xor_sync(0xffffffffu, mx1, 1));
        mx1 = fmaxf(mx1, __shfl_xor_sync(0xffffffffu, mx1, 2));
        float mn0 = fmaxf(m0, mx0), mn1 = fmaxf(m1, mx1);
        float a0 = __expf(m0 - mn0), a1 = __expf(m1 - mn1);
        float sum0 = 0.f, sum1 = 0.f;
        #pragma unroll
        for (int nt = 0; nt < 8; nt++) {
            s[nt][0] = __expf(s[nt][0] - mn0);
            s[nt][1] = __expf(s[nt][1] - mn0);
            s[nt][2] = __expf(s[nt][2] - mn1);
            s[nt][3] = __expf(s[nt][3] - mn1);
            sum0 += s[nt][0] + s[nt][1];
            sum1 += s[nt][2] + s[nt][3];
        }
        sum0 += __shfl_xor_sync(0xffffffffu, sum0, 1);
        sum0 += __shfl_xor_sync(0xffffffffu, sum0, 2);
        sum1 += __shfl_xor_sync(0xffffffffu, sum1, 1);
        sum1 += __shfl_xor_sync(0xffffffffu, sum1, 2);
        l0 = l0 * a0 + sum0; m0 = mn0;
        l1 = l1 * a1 + sum1; m1 = mn1;
        #pragma unroll
        for (int nt = 0; nt < 8; nt++) {
            acc_o[nt][0] *= a0; acc_o[nt][1] *= a0;
            acc_o[nt][2] *= a1; acc_o[nt][3] *= a1;
        }

        uint32_t phi[4][4], plo[4][4];
        #pragma unroll
        for (int j2 = 0; j2 < 4; j2++) {
            float r0a, r0b, r1a, r1b, r2a, r2b, r3a, r3b;
            phi[j2][0] = pack_hilo(s[2*j2][0],   s[2*j2][1],   &r0a, &r0b);
            phi[j2][1] = pack_hilo(s[2*j2][2],   s[2*j2][3],   &r1a, &r1b);
            phi[j2][2] = pack_hilo(s[2*j2+1][0], s[2*j2+1][1], &r2a, &r2b);
            phi[j2][3] = pack_hilo(s[2*j2+1][2], s[2*j2+1][3], &r3a, &r3b);
            plo[j2][0] = pack_bf(r0a, r0b);
            plo[j2][1] = pack_bf(r1a, r1b);
            plo[j2][2] = pack_bf(r2a, r2b);
            plo[j2][3] = pack_bf(r3a, r3b);
        }

        #pragma unroll
        for (int j2 = 0; j2 < 4; j2++) {
            int vrow = j2 * 16 + vrow_off;
            #pragma unroll
            for (int g = 0; g < 4; g++) {
                int cg = g * 2 + vcg;
                uint32_t off = (uint32_t)(vrow * 128 + ((cg ^ (vrow & 7)) * 16));
                uint32_t vh[4], vl[4];
                ldsm4t(vh, st + 16384 + off);
                ldsm4t(vl, st + 24576 + off);
                mma_bf16(acc_o[2*g],     phi[j2], &vh[0]);
                mma_bf16(acc_o[2*g],     phi[j2], &vl[0]);
                mma_bf16(acc_o[2*g],     plo[j2], &vh[0]);
                mma_bf16(acc_o[2*g + 1], phi[j2], &vh[2]);
                mma_bf16(acc_o[2*g + 1], phi[j2], &vl[2]);
                mma_bf16(acc_o[2*g + 1], plo[j2], &vh[2]);
            }
        }
        __syncthreads();
    }

    const int b = bh >> 4, h = bh & 15;
    const float inv0 = 1.f / l0, inv1 = 1.f / l1;
    #pragma unroll
    for (int nt = 0; nt < 8; nt++) {
        int d = nt * 8 + 2 * (lane & 3);
        float f0 = acc_o[nt][0] * inv0, f1 = acc_o[nt][1] * inv0;
        float f2 = acc_o[nt][2] * inv1, f3 = acc_o[nt][3] * inv1;
        size_t o0 = ((size_t)(b * TSEQ + r0g)) * DM + h * HD + d;
        size_t o1 = ((size_t)(b * TSEQ + r1g)) * DM + h * HD + d;
        __nv_bfloat16 h0 = __float2bfloat16(f0), h1 = __float2bfloat16(f1);
        __nv_bfloat16 h2 = __float2bfloat16(f2), h3 = __float2bfloat16(f3);
        *(ushort2*)&ohi[o0] = make_ushort2(bfbits(h0), bfbits(h1));
        *(ushort2*)&ohi[o1] = make_ushort2(bfbits(h2), bfbits(h3));
        *(ushort2*)&olo[o0] = make_ushort2(
            bfbits(__float2bfloat16(f0 - __bfloat162float(h0))),
            bfbits(__float2bfloat16(f1 - __bfloat162float(h1))));
        *(ushort2*)&olo[o1] = make_ushort2(
            bfbits(__float2bfloat16(f2 - __bfloat162float(h2))),
            bfbits(__float2bfloat16(f3 - __bfloat162float(h3))));
    }
}

// ---------------------------------------------------------------------------
extern "C" void kernel_launch(void* const* d_in, const int* in_sizes, int n_in,
                              void* d_out, int out_size)
{
    (void)in_sizes; (void)n_in; (void)out_size;
    const float* x     = (const float*)d_in[0];
    const float* qkv_w = (const float*)d_in[1];
    const float* qkv_b = (const float*)d_in[2];
    const float* out_w = (const float*)d_in[3];
    const float* out_b = (const float*)d_in[4];
    float* out = (float*)d_out;

    __nv_bfloat16 *xhi, *xlo, *w1hi, *w1lo, *w2hi, *w2lo, *ahi, *alo;
    __nv_bfloat16 *qhi, *qlo, *khi, *klo, *vhi, *vlo;
    cudaGetSymbolAddress((void**)&xhi,  g_xhi);  cudaGetSymbolAddress((void**)&xlo,  g_xlo);
    cudaGetSymbolAddress((void**)&w1hi, g_w1hi); cudaGetSymbolAddress((void**)&w1lo, g_w1lo);
    cudaGetSymbolAddress((void**)&w2hi, g_w2hi); cudaGetSymbolAddress((void**)&w2lo, g_w2lo);
    cudaGetSymbolAddress((void**)&ahi,  g_ahi);  cudaGetSymbolAddress((void**)&alo,  g_alo);
    cudaGetSymbolAddress((void**)&qhi,  g_qhi);  cudaGetSymbolAddress((void**)&qlo,  g_qlo);
    cudaGetSymbolAddress((void**)&khi,  g_khi);  cudaGetSymbolAddress((void**)&klo,  g_klo);
    cudaGetSymbolAddress((void**)&vhi,  g_vhi);  cudaGetSymbolAddress((void**)&vlo,  g_vlo);

    cudaFuncSetAttribute(mma_gemm<true>,  cudaFuncAttributeMaxDynamicSharedMemorySize, GEMM_SMEM);
    cudaFuncSetAttribute(mma_gemm<false>, cudaFuncAttributeMaxDynamicSharedMemorySize, GEMM_SMEM);
    cudaFuncSetAttribute(flash_mma, cudaFuncAttributeMaxDynamicSharedMemorySize, FL_SMEM);

    split_kernel<<<(MTOT*DM/4 + 255)/256, 256>>>(x, xhi, xlo, MTOT*DM/4);
    split_kernel<<<(3*DM*DM/4 + 255)/256, 256>>>(qkv_w, w1hi, w1lo, 3*DM*DM/4);
    split_kernel<<<(DM*DM/4 + 255)/256, 256>>>(out_w, w2hi, w2lo, DM*DM/4);

    dim3 g1(3*DM/128, MTOT/128);
    mma_gemm<true><<<g1, 256, GEMM_SMEM>>>(xhi, xlo, w1hi, w1lo, qkv_b, nullptr, 3*DM);

    dim3 g2(TSEQ/128, BDIM*NH);
    flash_mma<<<g2, 256, FL_SMEM>>>(qhi, qlo, khi, klo, vhi, vlo, ahi, alo);

    dim3 g3(DM/128, MTOT/128);
    mma_gemm<false><<<g3, 256, GEMM_SMEM>>>(ahi, alo, w2hi, w2lo, out_b, out, DM);
}

// round 6
// speedup vs baseline: 3.1062x; 1.0181x over previous
#include <cuda_runtime.h>
#include <cuda_bf16.h>
#include <cstdint>

#define BDIM 2
#define TSEQ 2048
#define NH 16
#define HD 64
#define DM 1024
#define MTOT (BDIM*TSEQ)

// ---------------- scratch (allocation-free: __device__ globals) ----------------
__device__ uint4 g_xhi[(size_t)MTOT*DM*2/16],  g_xlo[(size_t)MTOT*DM*2/16];
__device__ uint4 g_w1hi[(size_t)3*DM*DM*2/16], g_w1lo[(size_t)3*DM*DM*2/16];
__device__ uint4 g_w2hi[(size_t)DM*DM*2/16],   g_w2lo[(size_t)DM*DM*2/16];
__device__ uint4 g_qhi[(size_t)BDIM*NH*TSEQ*HD*2/16];
__device__ uint4 g_khi[(size_t)BDIM*NH*TSEQ*HD*2/16], g_klo[(size_t)BDIM*NH*TSEQ*HD*2/16];
__device__ uint4 g_vhi[(size_t)BDIM*NH*TSEQ*HD*2/16], g_vlo[(size_t)BDIM*NH*TSEQ*HD*2/16];
__device__ uint4 g_ahi[(size_t)MTOT*DM*2/16],  g_alo[(size_t)MTOT*DM*2/16];

// ---------------- helpers ----------------
__device__ __forceinline__ uint32_t smem_u32(const void* p) {
    uint32_t a;
    asm("{ .reg .u64 t; cvta.to.shared.u64 t, %1; cvt.u32.u64 %0, t; }" : "=r"(a) : "l"(p));
    return a;
}
__device__ __forceinline__ void cpasync16(uint32_t dst, const void* src) {
    asm volatile("cp.async.cg.shared.global [%0], [%1], 16;" :: "r"(dst), "l"(src) : "memory");
}
__device__ __forceinline__ void ldsm4(uint32_t* r, uint32_t addr) {
    asm volatile("ldmatrix.sync.aligned.m8n8.x4.shared.b16 {%0,%1,%2,%3}, [%4];"
        : "=r"(r[0]), "=r"(r[1]), "=r"(r[2]), "=r"(r[3]) : "r"(addr));
}
__device__ __forceinline__ void ldsm4t(uint32_t* r, uint32_t addr) {
    asm volatile("ldmatrix.sync.aligned.m8n8.x4.trans.shared.b16 {%0,%1,%2,%3}, [%4];"
        : "=r"(r[0]), "=r"(r[1]), "=r"(r[2]), "=r"(r[3]) : "r"(addr));
}
__device__ __forceinline__ void mma_bf16(float* c, const uint32_t* a, const uint32_t* b) {
    asm volatile(
        "mma.sync.aligned.m16n8k16.row.col.f32.bf16.bf16.f32 "
        "{%0,%1,%2,%3}, {%4,%5,%6,%7}, {%8,%9}, {%0,%1,%2,%3};"
        : "+f"(c[0]), "+f"(c[1]), "+f"(c[2]), "+f"(c[3])
        : "r"(a[0]), "r"(a[1]), "r"(a[2]), "r"(a[3]), "r"(b[0]), "r"(b[1]));
}
__device__ __forceinline__ unsigned short bfbits(__nv_bfloat16 h) {
    return reinterpret_cast<unsigned short&>(h);
}
__device__ __forceinline__ uint32_t pack_hilo(float a, float b, float* ra, float* rb) {
    __nv_bfloat16 ha = __float2bfloat16(a), hb = __float2bfloat16(b);
    *ra = a - __bfloat162float(ha);
    *rb = b - __bfloat162float(hb);
    return (uint32_t)bfbits(ha) | ((uint32_t)bfbits(hb) << 16);
}
__device__ __forceinline__ uint32_t pack_bf(float a, float b) {
    return (uint32_t)bfbits(__float2bfloat16(a)) | ((uint32_t)bfbits(__float2bfloat16(b)) << 16);
}

// ---------------- fused fp32 -> bf16 hi/lo split over 3 tensors ----------------
#define SPLIT_N0 (MTOT*DM/4)
#define SPLIT_N1 (3*DM*DM/4)
#define SPLIT_N2 (DM*DM/4)
#define SPLIT_TOT (SPLIT_N0 + SPLIT_N1 + SPLIT_N2)

__global__ __launch_bounds__(256)
void split3_kernel(const float* __restrict__ s0, const float* __restrict__ s1,
                   const float* __restrict__ s2)
{
    int i = blockIdx.x * blockDim.x + threadIdx.x;
    if (i >= SPLIT_TOT) return;
    const float* s; __nv_bfloat16 *hi, *lo; int j;
    if (i < SPLIT_N0) {
        s = s0; hi = (__nv_bfloat16*)g_xhi; lo = (__nv_bfloat16*)g_xlo; j = i;
    } else if (i < SPLIT_N0 + SPLIT_N1) {
        s = s1; hi = (__nv_bfloat16*)g_w1hi; lo = (__nv_bfloat16*)g_w1lo; j = i - SPLIT_N0;
    } else {
        s = s2; hi = (__nv_bfloat16*)g_w2hi; lo = (__nv_bfloat16*)g_w2lo; j = i - SPLIT_N0 - SPLIT_N1;
    }
    float4 v = ((const float4*)s)[j];
    float f[4] = {v.x, v.y, v.z, v.w};
    unsigned short h[4], l[4];
    #pragma unroll
    for (int k = 0; k < 4; k++) {
        __nv_bfloat16 hb = __float2bfloat16(f[k]);
        __nv_bfloat16 lb = __float2bfloat16(f[k] - __bfloat162float(hb));
        h[k] = bfbits(hb); l[k] = bfbits(lb);
    }
    ((ushort4*)hi)[j] = make_ushort4(h[0], h[1], h[2], h[3]);
    ((ushort4*)lo)[j] = make_ushort4(l[0], l[1], l[2], l[3]);
}

// ---------------- persistent mma.sync GEMM (128-reg / 2-CTA) ----------------
#define BK 32
#define NCH (DM / BK)
#define TILE_B 8192
#define STAGE_B (4 * TILE_B)
#define GEMM_SMEM (2 * STAGE_B)

template<bool SCATTER>
__global__ __launch_bounds__(256, 2)
void mma_gemm(const __nv_bfloat16* __restrict__ Ahi, const __nv_bfloat16* __restrict__ Alo,
              const __nv_bfloat16* __restrict__ Whi, const __nv_bfloat16* __restrict__ Wlo,
              const float* __restrict__ bias, float* __restrict__ C, int N)
{
    extern __shared__ char smem[];
    const uint32_t sbase = smem_u32(smem);
    const int tid = threadIdx.x, wid = tid >> 5, lane = tid & 31;
    const int wm = wid & 3, wn = wid >> 2;
    const int K = DM;
    const int nx = N >> 7;
    const int ntile = (MTOT >> 7) * nx;

    auto load_stage = [&](int m0, int n0, int c, int stg) {
        const uint32_t st = sbase + (uint32_t)stg * STAGE_B;
        const int k0 = c * BK;
        #pragma unroll
        for (int t = 0; t < 2; t++) {
            int idx = tid + t * 256;
            int row = idx >> 2, ch = idx & 3;
            uint32_t so = (uint32_t)(row * 64 + ((ch ^ ((row >> 1) & 3)) * 16));
            int gk = k0 + ch * 8;
            const size_t ea = (size_t)(m0 + row) * K + gk;
            const size_t ew = (size_t)(n0 + row) * K + gk;
            cpasync16(st + so,              Ahi + ea);
            cpasync16(st + TILE_B + so,     Alo + ea);
            cpasync16(st + 2*TILE_B + so,   Whi + ew);
            cpasync16(st + 3*TILE_B + so,   Wlo + ew);
        }
        asm volatile("cp.async.commit_group;" ::: "memory");
    };

    const int arowoff = lane & 15;
    const int akoff   = lane >> 4;
    const int browoff = (lane & 7) + ((lane >> 4) << 3);
    const int bkoff   = (lane >> 3) & 1;

    int rowA[2], swA[2];
    #pragma unroll
    for (int mt = 0; mt < 2; mt++) {
        rowA[mt] = wm * 32 + mt * 16 + arowoff;
        swA[mt]  = (rowA[mt] >> 1) & 3;
    }
    int rowB[4], swB[4];
    #pragma unroll
    for (int nt2 = 0; nt2 < 4; nt2++) {
        rowB[nt2] = wn * 64 + nt2 * 16 + browoff;
        swB[nt2]  = (rowB[nt2] >> 1) & 3;
    }

    // prime: first tile's chunk 0
    {
        int t0 = blockIdx.x;
        if (t0 < ntile) load_stage((t0 / nx) << 7, (t0 % nx) << 7, 0, 0);
    }

    for (int tile = blockIdx.x; tile < ntile; tile += gridDim.x) {
        const int m0 = (tile / nx) << 7, n0 = (tile % nx) << 7;
        const int tnext = tile + gridDim.x;
        const bool has_next = tnext < ntile;
        const int mn = has_next ? ((tnext / nx) << 7) : 0;
        const int nn = has_next ? ((tnext % nx) << 7) : 0;

        float acc[2][8][4];
        #pragma unroll
        for (int mt = 0; mt < 2; mt++)
            #pragma unroll
            for (int nt = 0; nt < 8; nt++)
                #pragma unroll
                for (int q = 0; q < 4; q++) acc[mt][nt][q] = 0.f;

        for (int c = 0; c < NCH; c++) {
            const int cur = c & 1;
            if (c + 1 < NCH) {
                load_stage(m0, n0, c + 1, cur ^ 1);
                asm volatile("cp.async.wait_group 1;" ::: "memory");
            } else if (has_next) {
                load_stage(mn, nn, 0, 0);   // (NCH-1)&1 ^ 1 == 0
                asm volatile("cp.async.wait_group 1;" ::: "memory");
            } else {
                asm volatile("cp.async.wait_group 0;" ::: "memory");
            }
            __syncthreads();

            const uint32_t st = sbase + (uint32_t)cur * STAGE_B;
            #pragma unroll
            for (int s = 0; s < 2; s++) {
                uint32_t ahi[2][4], alo[2][4];
                #pragma unroll
                for (int mt = 0; mt < 2; mt++) {
                    uint32_t off = (uint32_t)(rowA[mt] * 64 + (((2*s + akoff) ^ swA[mt]) * 16));
                    ldsm4(ahi[mt], st + off);
                    ldsm4(alo[mt], st + TILE_B + off);
                }
                uint32_t bhi[4][4], blo[4][4];
                #pragma unroll
                for (int nt2 = 0; nt2 < 4; nt2++) {
                    uint32_t off = (uint32_t)(rowB[nt2] * 64 + (((2*s + bkoff) ^ swB[nt2]) * 16));
                    ldsm4(bhi[nt2], st + 2*TILE_B + off);
                    ldsm4(blo[nt2], st + 3*TILE_B + off);
                }
                #pragma unroll
                for (int mt = 0; mt < 2; mt++)
                    #pragma unroll
                    for (int nt = 0; nt < 8; nt++) {
                        const uint32_t* bh = &bhi[nt >> 1][(nt & 1) * 2];
                        const uint32_t* bl = &blo[nt >> 1][(nt & 1) * 2];
                        mma_bf16(acc[mt][nt], ahi[mt], bh);
                        mma_bf16(acc[mt][nt], ahi[mt], bl);
                        mma_bf16(acc[mt][nt], alo[mt], bh);
                    }
            }
            __syncthreads();
        }

        const int lr = lane >> 2, lc = (lane & 3) * 2;
        #pragma unroll
        for (int mt = 0; mt < 2; mt++) {
            #pragma unroll
            for (int half = 0; half < 2; half++) {
                const int m = m0 + wm * 32 + mt * 16 + lr + half * 8;
                #pragma unroll
                for (int nt = 0; nt < 8; nt++) {
                    const int n = n0 + wn * 64 + nt * 8 + lc;
                    float rx = acc[mt][nt][half * 2 + 0] + bias[n + 0];
                    float ry = acc[mt][nt][half * 2 + 1] + bias[n + 1];
                    if (!SCATTER) {
                        *(float2*)&C[(size_t)m * N + n] = make_float2(rx, ry);
                    } else {
                        int mat = n >> 10, h = (n >> 6) & 15, d = n & 63;
                        int b = m >> 11, t = m & 2047;
                        if (mat == 0) { rx *= 0.125f; ry *= 0.125f; }
                        __nv_bfloat16 hx = __float2bfloat16(rx), hy = __float2bfloat16(ry);
                        __nv_bfloat16* dh = (mat == 0) ? (__nv_bfloat16*)g_qhi
                                           : (mat == 1) ? (__nv_bfloat16*)g_khi : (__nv_bfloat16*)g_vhi;
                        size_t off = (((size_t)(b * NH + h) * TSEQ) + t) * HD + d;
                        *(ushort2*)&dh[off] = make_ushort2(bfbits(hx), bfbits(hy));
                        if (mat != 0) {
                            unsigned short lx = bfbits(__float2bfloat16(rx - __bfloat162float(hx)));
                            unsigned short ly = bfbits(__float2bfloat16(ry - __bfloat162float(hy)));
                            __nv_bfloat16* dl = (mat == 1) ? (__nv_bfloat16*)g_klo : (__nv_bfloat16*)g_vlo;
                            *(ushort2*)&dl[off] = make_ushort2(lx, ly);
                        }
                    }
                }
            }
        }
    }
}

// ---------------- flash attention (Q bf16 single, K hi/lo 2-pass S, PV 3-pass) ----------------
#define FL_QHI 0u
#define FL_STG 16384u
#define FL_SSZ 32768u
#define FL_SMEM (FL_STG + 2 * FL_SSZ)   // 81920

__global__ __launch_bounds__(256, 1)
void flash_mma(const __nv_bfloat16* __restrict__ qhi,
               const __nv_bfloat16* __restrict__ khi, const __nv_bfloat16* __restrict__ klo,
               const __nv_bfloat16* __restrict__ vhi, const __nv_bfloat16* __restrict__ vlo,
               __nv_bfloat16* __restrict__ ohi, __nv_bfloat16* __restrict__ olo)
{
    extern __shared__ char smem[];
    const uint32_t sb = smem_u32(smem);
    const int tid = threadIdx.x, wid = tid >> 5, lane = tid & 31;
    const int bh = blockIdx.y;
    const int qb = gridDim.x - 1 - blockIdx.x;     // heavy tiles first
    const int qbase = qb * 128;
    const size_t base = (size_t)bh * TSEQ * HD;
    const int nkb = 2 * qb + 2;

    auto ldq = [&]() {
        #pragma unroll
        for (int t = 0; t < 4; t++) {
            int idx = tid + t * 256;
            int row = idx >> 3, ch = idx & 7;
            uint32_t so = (uint32_t)(row * 128 + ((ch ^ (row & 7)) * 16));
            size_t g = base + (size_t)(qbase + row) * HD + ch * 8;
            cpasync16(sb + FL_QHI + so, qhi + g);
        }
    };
    auto ldkv = [&](int kb, int stg) {
        const uint32_t st = sb + FL_STG + (uint32_t)stg * FL_SSZ;
        #pragma unroll
        for (int t = 0; t < 2; t++) {
            int idx = tid + t * 256;
            int row = idx >> 3, ch = idx & 7;
            uint32_t so = (uint32_t)(row * 128 + ((ch ^ (row & 7)) * 16));
            size_t g = base + (size_t)(kb * 64 + row) * HD + ch * 8;
            cpasync16(st + so,          khi + g);
            cpasync16(st + 8192 + so,   klo + g);
            cpasync16(st + 16384 + so,  vhi + g);
            cpasync16(st + 24576 + so,  vlo + g);
        }
        asm volatile("cp.async.commit_group;" ::: "memory");
    };

    ldq();
    ldkv(0, 0);

    const int arow = wid * 16 + (lane & 15);
    const int akoff = lane >> 4;
    const int brow_off = (lane & 7) + ((lane >> 4) << 3);
    const int bkoff = (lane >> 3) & 1;
    const int vrow_off = (lane & 7) + (((lane >> 3) & 1) << 3);
    const int vcg = lane >> 4;

    uint32_t qh[4][4];
    float acc_o[8][4];
    #pragma unroll
    for (int nt = 0; nt < 8; nt++)
        #pragma unroll
        for (int q = 0; q < 4; q++) acc_o[nt][q] = 0.f;
    float m0 = -1e30f, m1 = -1e30f, l0 = 0.f, l1 = 0.f;

    const int r0g = qbase + wid * 16 + (lane >> 2);
    const int r1g = r0g + 8;

    for (int kb = 0; kb < nkb; kb++) {
        const int cur = kb & 1;
        if (kb + 1 < nkb) {
            ldkv(kb + 1, cur ^ 1);
            asm volatile("cp.async.wait_group 1;" ::: "memory");
        } else {
            asm volatile("cp.async.wait_group 0;" ::: "memory");
        }
        __syncthreads();

        if (kb == 0) {
            #pragma unroll
            for (int s4 = 0; s4 < 4; s4++) {
                uint32_t off = (uint32_t)(arow * 128 + (((2*s4 + akoff) ^ (arow & 7)) * 16));
                ldsm4(qh[s4], sb + FL_QHI + off);
            }
        }

        const uint32_t st = sb + FL_STG + (uint32_t)cur * FL_SSZ;

        float s[8][4];
        #pragma unroll
        for (int nt = 0; nt < 8; nt++)
            #pragma unroll
            for (int q = 0; q < 4; q++) s[nt][q] = 0.f;

        #pragma unroll
        for (int s4 = 0; s4 < 4; s4++) {
            uint32_t kh[4][4], kl[4][4];
            #pragma unroll
            for (int nt2 = 0; nt2 < 4; nt2++) {
                int row = nt2 * 16 + brow_off;
                uint32_t off = (uint32_t)(row * 128 + (((2*s4 + bkoff) ^ (row & 7)) * 16));
                ldsm4(kh[nt2], st + off);
                ldsm4(kl[nt2], st + 8192 + off);
            }
            #pragma unroll
            for (int nt = 0; nt < 8; nt++) {
                const uint32_t* bh_ = &kh[nt >> 1][(nt & 1) * 2];
                const uint32_t* bl_ = &kl[nt >> 1][(nt & 1) * 2];
                mma_bf16(s[nt], qh[s4], bh_);
                mma_bf16(s[nt], qh[s4], bl_);
            }
        }

        const int kbase = kb * 64;
        if (kb >= nkb - 2) {
            #pragma unroll
            for (int nt = 0; nt < 8; nt++) {
                int kg0 = kbase + nt * 8 + 2 * (lane & 3);
                if (kg0 > r0g)     s[nt][0] = -1e30f;
                if (kg0 + 1 > r0g) s[nt][1] = -1e30f;
                if (kg0 > r1g)     s[nt][2] = -1e30f;
                if (kg0 + 1 > r1g) s[nt][3] = -1e30f;
            }
        }

        float mx0 = -1e30f, mx1 = -1e30f;
        #pragma unroll
        for (int nt = 0; nt < 8; nt++) {
            mx0 = fmaxf(mx0, fmaxf(s[nt][0], s[nt][1]));
            mx1 = fmaxf(mx1, fmaxf(s[nt][2], s[nt][3]));
        }
        mx0 = fmaxf(mx0, __shfl_xor_sync(0xffffffffu, mx0, 1));
        mx0 = fmaxf(mx0, __shfl_xor_sync(0xffffffffu, mx0, 2));
        mx1 = fmaxf(mx1, __shfl_xor_sync(0xffffffffu, mx1, 1));
        mx1 = fmaxf(mx1, __shfl_xor_sync(0xffffffffu, mx1, 2));
        float mn0 = fmaxf(m0, mx0), mn1 = fmaxf(m1, mx1);
        float a0 = __expf(m0 - mn0), a1 = __expf(m1 - mn1);
        float sum0 = 0.f, sum1 = 0.f;
        #pragma unroll
        for (int nt = 0; nt < 8; nt++) {
            s[nt][0] = __expf(s[nt][0] - mn0);
            s[nt][1] = __expf(s[nt][1] - mn0);
            s[nt][2] = __expf(s[nt][2] - mn1);
            s[nt][3] = __expf(s[nt][3] - mn1);
            sum0 += s[nt][0] + s[nt][1];
            sum1 += s[nt][2] + s[nt][3];
        }
        sum0 += __shfl_xor_sync(0xffffffffu, sum0, 1);
        sum0 += __shfl_xor_sync(0xffffffffu, sum0, 2);
        sum1 += __shfl_xor_sync(0xffffffffu, sum1, 1);
        sum1 += __shfl_xor_sync(0xffffffffu, sum1, 2);
        l0 = l0 * a0 + sum0; m0 = mn0;
        l1 = l1 * a1 + sum1; m1 = mn1;
        #pragma unroll
        for (int nt = 0; nt < 8; nt++) {
            acc_o[nt][0] *= a0; acc_o[nt][1] *= a0;
            acc_o[nt][2] *= a1; acc_o[nt][3] *= a1;
        }

        uint32_t phi[4][4], plo[4][4];
        #pragma unroll
        for (int j2 = 0; j2 < 4; j2++) {
            float r0a, r0b, r1a, r1b, r2a, r2b, r3a, r3b;
            phi[j2][0] = pack_hilo(s[2*j2][0],   s[2*j2][1],   &r0a, &r0b);
            phi[j2][1] = pack_hilo(s[2*j2][2],   s[2*j2][3],   &r1a, &r1b);
            phi[j2][2] = pack_hilo(s[2*j2+1][0], s[2*j2+1][1], &r2a, &r2b);
            phi[j2][3] = pack_hilo(s[2*j2+1][2], s[2*j2+1][3], &r3a, &r3b);
            plo[j2][0] = pack_bf(r0a, r0b);
            plo[j2][1] = pack_bf(r1a, r1b);
            plo[j2][2] = pack_bf(r2a, r2b);
            plo[j2][3] = pack_bf(r3a, r3b);
        }

        #pragma unroll
        for (int j2 = 0; j2 < 4; j2++) {
            int vrow = j2 * 16 + vrow_off;
            #pragma unroll
            for (int g = 0; g < 4; g++) {
                int cg = g * 2 + vcg;
                uint32_t off = (uint32_t)(vrow * 128 + ((cg ^ (vrow & 7)) * 16));
                uint32_t vh[4], vl[4];
                ldsm4t(vh, st + 16384 + off);
                ldsm4t(vl, st + 24576 + off);
                mma_bf16(acc_o[2*g],     phi[j2], &vh[0]);
                mma_bf16(acc_o[2*g],     phi[j2], &vl[0]);
                mma_bf16(acc_o[2*g],     plo[j2], &vh[0]);
                mma_bf16(acc_o[2*g + 1], phi[j2], &vh[2]);
                mma_bf16(acc_o[2*g + 1], phi[j2], &vl[2]);
                mma_bf16(acc_o[2*g + 1], plo[j2], &vh[2]);
            }
        }
        __syncthreads();
    }

    const int b = bh >> 4, h = bh & 15;
    const float inv0 = 1.f / l0, inv1 = 1.f / l1;
    #pragma unroll
    for (int nt = 0; nt < 8; nt++) {
        int d = nt * 8 + 2 * (lane & 3);
        float f0 = acc_o[nt][0] * inv0, f1 = acc_o[nt][1] * inv0;
        float f2 = acc_o[nt][2] * inv1, f3 = acc_o[nt][3] * inv1;
        size_t o0 = ((size_t)(b * TSEQ + r0g)) * DM + h * HD + d;
        size_t o1 = ((size_t)(b * TSEQ + r1g)) * DM + h * HD + d;
        __nv_bfloat16 h0 = __float2bfloat16(f0), h1 = __float2bfloat16(f1);
        __nv_bfloat16 h2 = __float2bfloat16(f2), h3 = __float2bfloat16(f3);
        *(ushort2*)&ohi[o0] = make_ushort2(bfbits(h0), bfbits(h1));
        *(ushort2*)&ohi[o1] = make_ushort2(bfbits(h2), bfbits(h3));
        *(ushort2*)&olo[o0] = make_ushort2(
            bfbits(__float2bfloat16(f0 - __bfloat162float(h0))),
            bfbits(__float2bfloat16(f1 - __bfloat162float(h1))));
        *(ushort2*)&olo[o1] = make_ushort2(
            bfbits(__float2bfloat16(f2 - __bfloat162float(h2))),
            bfbits(__float2bfloat16(f3 - __bfloat162float(h3))));
    }
}

// ---------------------------------------------------------------------------
extern "C" void kernel_launch(void* const* d_in, const int* in_sizes, int n_in,
                              void* d_out, int out_size)
{
    (void)in_sizes; (void)n_in; (void)out_size;
    const float* x     = (const float*)d_in[0];
    const float* qkv_w = (const float*)d_in[1];
    const float* qkv_b = (const float*)d_in[2];
    const float* out_w = (const float*)d_in[3];
    const float* out_b = (const float*)d_in[4];
    float* out = (float*)d_out;

    __nv_bfloat16 *xhi, *xlo, *w1hi, *w1lo, *w2hi, *w2lo, *ahi, *alo;
    __nv_bfloat16 *qhi, *khi, *klo, *vhi, *vlo;
    cudaGetSymbolAddress((void**)&xhi,  g_xhi);  cudaGetSymbolAddress((void**)&xlo,  g_xlo);
    cudaGetSymbolAddress((void**)&w1hi, g_w1hi); cudaGetSymbolAddress((void**)&w1lo, g_w1lo);
    cudaGetSymbolAddress((void**)&w2hi, g_w2hi); cudaGetSymbolAddress((void**)&w2lo, g_w2lo);
    cudaGetSymbolAddress((void**)&ahi,  g_ahi);  cudaGetSymbolAddress((void**)&alo,  g_alo);
    cudaGetSymbolAddress((void**)&qhi,  g_qhi);
    cudaGetSymbolAddress((void**)&khi,  g_khi);  cudaGetSymbolAddress((void**)&klo,  g_klo);
    cudaGetSymbolAddress((void**)&vhi,  g_vhi);  cudaGetSymbolAddress((void**)&vlo,  g_vlo);

    cudaFuncSetAttribute(mma_gemm<true>,  cudaFuncAttributeMaxDynamicSharedMemorySize, GEMM_SMEM);
    cudaFuncSetAttribute(mma_gemm<false>, cudaFuncAttributeMaxDynamicSharedMemorySize, GEMM_SMEM);
    cudaFuncSetAttribute(flash_mma, cudaFuncAttributeMaxDynamicSharedMemorySize, FL_SMEM);

    // 0) fused bf16 hi/lo splits
    split3_kernel<<<(SPLIT_TOT + 255)/256, 256>>>(x, qkv_w, out_w);

    // 1) QKV projection (persistent) -> bf16 q(hi), k/v(hi,lo) in [B,H,T,Hd]
    {
        int ntile = (MTOT/128) * (3*DM/128);
        int grid = ntile < 296 ? ntile : 296;
        mma_gemm<true><<<grid, 256, GEMM_SMEM>>>(xhi, xlo, w1hi, w1lo, qkv_b, nullptr, 3*DM);
    }

    // 2) flash attention -> g_ahi/g_alo [B,T,D]
    dim3 g2(TSEQ/128, BDIM*NH);
    flash_mma<<<g2, 256, FL_SMEM>>>(qhi, khi, klo, vhi, vlo, ahi, alo);

    // 3) output projection (persistent) -> d_out
    {
        int ntile = (MTOT/128) * (DM/128);
        int grid = ntile < 296 ? ntile : 296;
        mma_gemm<false><<<grid, 256, GEMM_SMEM>>>(ahi, alo, w2hi, w2lo, out_b, out, DM);
    }
}